// round 4
// baseline (speedup 1.0000x reference)
#include <cuda_runtime.h>
#include <math.h>

#define BATCH   16384
#define NTAB    26
#define VOCABSZ 100000

// ---------------- scratch (bss, no allocation) ----------------
__device__ float g_x0[BATCH * 512];   // bottom L0 out
__device__ float g_x1[BATCH * 256];   // bottom L1 out
__device__ float g_h [BATCH * 416];   // [d(64) | inter(351) | zero pad(1)]
__device__ float g_h1[BATCH * 512];   // top L0 out
__device__ float g_h2[BATCH * 256];   // top L1 out

typedef unsigned long long u64;

// ---------------- packed f32x2 helpers (full-rate fp32 on sm_103a) --------
__device__ __forceinline__ u64 pk2(float lo, float hi) {
    u64 r; asm("mov.b64 %0, {%1,%2};" : "=l"(r) : "f"(lo), "f"(hi)); return r;
}
__device__ __forceinline__ void upk2(u64 v, float& lo, float& hi) {
    asm("mov.b64 {%0,%1}, %2;" : "=f"(lo), "=f"(hi) : "l"(v));
}
__device__ __forceinline__ void fma2(u64& c, u64 a, u64 b) {
    asm("fma.rn.f32x2 %0, %1, %2, %3;" : "=l"(c) : "l"(a), "l"(b), "l"(c));
}

// =====================================================================
// Bottom MLP layer 0: x0[16384,512] = relu(dense[16384,13] @ Wb0 + bb0)
// 32 rows per block, full weight matrix cached in smem.
// =====================================================================
__global__ void __launch_bounds__(256) bot0_kernel(
    const float* __restrict__ dense, const float* __restrict__ W,
    const float* __restrict__ bias, float* __restrict__ x0)
{
    __shared__ float sW[13 * 512];
    __shared__ float sB[512];
    __shared__ float sD[32 * 13];
    const int tid = threadIdx.x;
    const int rbase = blockIdx.x * 32;

    for (int i = tid; i < 13 * 512; i += 256) sW[i] = W[i];
    for (int i = tid; i < 512;      i += 256) sB[i] = bias[i];
    for (int i = tid; i < 32 * 13;  i += 256) sD[i] = dense[(size_t)rbase * 13 + i];
    __syncthreads();

    const int q  = tid & 127;     // which 4-col group (128 * 4 = 512)
    const int rs = tid >> 7;      // 0/1 -> 16-row half
    const int c0 = q * 4;

    float4 w[13];
#pragma unroll
    for (int k = 0; k < 13; k++) w[k] = *(const float4*)&sW[k * 512 + c0];
    const float4 bq = *(const float4*)&sB[c0];

    for (int rr = 0; rr < 16; rr++) {
        const int r = rs * 16 + rr;
        float4 acc = bq;
#pragma unroll
        for (int k = 0; k < 13; k++) {
            const float a = sD[r * 13 + k];
            acc.x += a * w[k].x; acc.y += a * w[k].y;
            acc.z += a * w[k].z; acc.w += a * w[k].w;
        }
        acc.x = fmaxf(acc.x, 0.f); acc.y = fmaxf(acc.y, 0.f);
        acc.z = fmaxf(acc.z, 0.f); acc.w = fmaxf(acc.w, 0.f);
        *(float4*)&x0[(size_t)(rbase + r) * 512 + c0] = acc;
    }
}

// =====================================================================
// Generic tiled SGEMM with fused bias + ReLU.
// C[M,N] = relu(A[M,K] @ W[K,N] + bias),  A row-major (lda), W row-major (N).
// BM=128, BK=16, 256 threads, thread tile 8 x TN, f32x2 packed accumulators
// (pairs along M, loaded straight from smem as 64-bit words).
// K handled via Ktiles*16 >= Kreal: A reads always in-bounds (lda padded),
// W rows k >= Kreal loaded as zero.
// =====================================================================
template<int BN, int TN>
__global__ void __launch_bounds__(256)
gemm_bias_relu(const float* __restrict__ A, int lda,
               const float* __restrict__ W, const float* __restrict__ bias,
               float* __restrict__ C, int ldc,
               int N, int Kreal, int Ktiles)
{
    constexpr int BM = 128, BK = 16, TM = 8;
    constexpr int NW = BN / 64;                 // W float4 loads per thread
    __shared__ float As[BK][BM + 4];            // padded: conflict-light
    __shared__ float Bs[BK][BN];

    const int tid  = threadIdx.x;
    const int bm   = blockIdx.y * BM;
    const int bn   = blockIdx.x * BN;
    const int colg = tid & 15;                  // 16 col groups
    const int rowg = tid >> 4;                  // 16 row groups (x8 rows)

    u64 acc[TM / 2][TN];
#pragma unroll
    for (int m = 0; m < TM / 2; m++)
#pragma unroll
        for (int n = 0; n < TN; n++) acc[m][n] = 0ull;   // (0.f,0.f)

    float4 pa[2], pw[NW];

    auto loadA = [&](int t) {
#pragma unroll
        for (int i = 0; i < 2; i++) {
            const int f = tid + i * 256;
            const int kq = f & 3, row = f >> 2;
            pa[i] = *(const float4*)(A + (size_t)(bm + row) * lda + t * BK + kq * 4);
        }
    };
    auto loadW = [&](int t) {
#pragma unroll
        for (int i = 0; i < NW; i++) {
            const int f  = tid + i * 256;
            const int kk = f / (BN / 4);
            const int nq = f % (BN / 4);
            const int kg = t * BK + kk;
            if (kg < Kreal)
                pw[i] = *(const float4*)(W + (size_t)kg * N + bn + nq * 4);
            else
                pw[i] = make_float4(0.f, 0.f, 0.f, 0.f);
        }
    };
    auto stage = [&]() {
#pragma unroll
        for (int i = 0; i < 2; i++) {
            const int f = tid + i * 256;
            const int kq = f & 3, row = f >> 2;
            As[kq * 4 + 0][row] = pa[i].x;
            As[kq * 4 + 1][row] = pa[i].y;
            As[kq * 4 + 2][row] = pa[i].z;
            As[kq * 4 + 3][row] = pa[i].w;
        }
#pragma unroll
        for (int i = 0; i < NW; i++) {
            const int f  = tid + i * 256;
            const int kk = f / (BN / 4), nq = f % (BN / 4);
            *(float4*)&Bs[kk][nq * 4] = pw[i];
        }
    };
    auto compute = [&]() {
#pragma unroll
        for (int k = 0; k < BK; k++) {
            const u64* ap = (const u64*)&As[k][rowg * 8];   // 4 row-pairs
            const u64 am0 = ap[0], am1 = ap[1], am2 = ap[2], am3 = ap[3];
            u64 bb[8];
            const float4 b0 = *(const float4*)&Bs[k][colg * TN];
            bb[0] = pk2(b0.x, b0.x); bb[1] = pk2(b0.y, b0.y);
            bb[2] = pk2(b0.z, b0.z); bb[3] = pk2(b0.w, b0.w);
            if (TN == 8) {
                const float4 b1 = *(const float4*)&Bs[k][colg * TN + 4];
                bb[4] = pk2(b1.x, b1.x); bb[5] = pk2(b1.y, b1.y);
                bb[6] = pk2(b1.z, b1.z); bb[7] = pk2(b1.w, b1.w);
            }
#pragma unroll
            for (int n = 0; n < TN; n++) {
                fma2(acc[0][n], am0, bb[n]);
                fma2(acc[1][n], am1, bb[n]);
                fma2(acc[2][n], am2, bb[n]);
                fma2(acc[3][n], am3, bb[n]);
            }
        }
    };

    loadA(0); loadW(0);
    stage();
    __syncthreads();
    for (int t = 1; t < Ktiles; ++t) {
        loadA(t); loadW(t);      // prefetch overlaps compute
        compute();
        __syncthreads();
        stage();
        __syncthreads();
    }
    compute();

    // ---------------- epilogue: bias + relu + store ----------------
    const int col0 = bn + colg * TN;
    float bv[TN];
#pragma unroll
    for (int n = 0; n < TN; n++) bv[n] = bias[col0 + n];
#pragma unroll
    for (int m = 0; m < TM / 2; m++) {
        const int r0 = bm + rowg * 8 + 2 * m;
        float o0[TN], o1[TN];
#pragma unroll
        for (int n = 0; n < TN; n++) {
            float lo, hi; upk2(acc[m][n], lo, hi);
            o0[n] = fmaxf(lo + bv[n], 0.f);
            o1[n] = fmaxf(hi + bv[n], 0.f);
        }
#pragma unroll
        for (int n = 0; n < TN; n += 4) {
            *(float4*)(C + (size_t)r0 * ldc + col0 + n) =
                make_float4(o0[n], o0[n + 1], o0[n + 2], o0[n + 3]);
            *(float4*)(C + (size_t)(r0 + 1) * ldc + col0 + n) =
                make_float4(o1[n], o1[n + 1], o1[n + 2], o1[n + 3]);
        }
    }
}

// =====================================================================
// Embedding gather + pairwise interaction.
// Per block: EROWS samples. smem T[r][28 vectors][stride 68] (vec 26 = d,
// vec 27 = zero pad). Pairs computed as 2x2 tiles over a 14x14 tile grid.
// Writes h[:, 64 + tril_idx] and zeroes h[:, 415].
// Index width (int32 vs int64, JAX x64 ambiguity) detected at runtime.
// =====================================================================
#define EROWS 6
#define VSTR  68   // float stride per vector (bank-decorrelating pad)

__global__ void __launch_bounds__(256) embed_interact_kernel(
    const u64* __restrict__ sidx, const float* __restrict__ emb,
    float* __restrict__ h)
{
    __shared__ float T[EROWS * 28 * VSTR];
    __shared__ int s_is32;
    const int tid = threadIdx.x;
    const int rbase = blockIdx.x * EROWS;

    if (tid == 0) {
        int f = 0;
#pragma unroll
        for (int i = 0; i < 16; i++)
            if (sidx[i] >> 32) f = 1;    // int64 indices always have hi=0
        s_is32 = f;
    }
    __syncthreads();
    const bool is32 = (s_is32 != 0);
    const int* sidx32 = (const int*)sidx;

    float4* T4 = (float4*)T;   // vector v of row r starts at (r*28+v)*17 float4

    // gather embeddings: EROWS*26 vectors x 16 float4
    for (int u = tid; u < EROWS * 26 * 16; u += 256) {
        const int v = u >> 4, f = u & 15;
        const int r = v / 26, t = v - r * 26;
        const int grow = rbase + r;
        if (grow < BATCH) {
            long long idx;
            if (is32) idx = (long long)sidx32[grow * 26 + t];
            else      idx = (long long)sidx[grow * 26 + t];
            const float4* src =
                (const float4*)(emb + ((size_t)t * VOCABSZ + (size_t)idx) * 64);
            T4[(r * 28 + t) * 17 + f] = src[f];
        }
    }
    // d rows (h cols 0..63) -> vector 26 ; zero vector 27
    for (int u = tid; u < EROWS * 16; u += 256) {
        const int r = u >> 4, f = u & 15;
        const int grow = rbase + r;
        if (grow < BATCH)
            T4[(r * 28 + 26) * 17 + f] = *(const float4*)(h + (size_t)grow * 416 + f * 4);
        T4[(r * 28 + 27) * 17 + f] = make_float4(0.f, 0.f, 0.f, 0.f);
    }
    if (tid < EROWS) {
        const int grow = rbase + tid;
        if (grow < BATCH) h[(size_t)grow * 416 + 415] = 0.f;   // K-pad column
    }
    __syncthreads();

    // interaction: 105 tile-tasks per row (91 full 2x2 tiles + 14 diagonal)
    for (int task = tid; task < EROWS * 105; task += 256) {
        const int r = task / 105, tt = task - r * 105;
        const int grow = rbase + r;
        if (grow >= BATCH) continue;
        float* hrow = h + (size_t)grow * 416 + 64;
        const float4* base = (const float4*)T + (size_t)r * 28 * 17;

        if (tt < 91) {
            int ti = 1;
            while ((ti * (ti + 1)) / 2 <= tt) ti++;        // ti in 1..13
            const int tj = tt - ti * (ti - 1) / 2;         // tj < ti
            const int i0 = 2 * ti, i1 = i0 + 1, j0 = 2 * tj, j1 = j0 + 1;
            const float4* Ti0 = base + i0 * 17;
            const float4* Ti1 = base + i1 * 17;
            const float4* Tj0 = base + j0 * 17;
            const float4* Tj1 = base + j1 * 17;
            float a00 = 0.f, a01 = 0.f, a10 = 0.f, a11 = 0.f;
#pragma unroll
            for (int f = 0; f < 16; f++) {
                const float4 x0 = Ti0[f], x1 = Ti1[f];
                const float4 y0 = Tj0[f], y1 = Tj1[f];
                a00 += x0.x * y0.x + x0.y * y0.y + x0.z * y0.z + x0.w * y0.w;
                a01 += x0.x * y1.x + x0.y * y1.y + x0.z * y1.z + x0.w * y1.w;
                a10 += x1.x * y0.x + x1.y * y0.y + x1.z * y0.z + x1.w * y0.w;
                a11 += x1.x * y1.x + x1.y * y1.y + x1.z * y1.z + x1.w * y1.w;
            }
            hrow[i0 * (i0 - 1) / 2 + j0] = a00;
            hrow[i0 * (i0 - 1) / 2 + j1] = a01;
            if (i1 < 27) {                                 // i1==27 is pad
                hrow[i1 * (i1 - 1) / 2 + j0] = a10;
                hrow[i1 * (i1 - 1) / 2 + j1] = a11;
            }
        } else {
            const int ti = tt - 91;
            const int i = 2 * ti + 1, j = 2 * ti;
            if (i < 27) {
                const float4* Ti = base + i * 17;
                const float4* Tj = base + j * 17;
                float a = 0.f;
#pragma unroll
                for (int f = 0; f < 16; f++) {
                    const float4 x = Ti[f], y = Tj[f];
                    a += x.x * y.x + x.y * y.y + x.z * y.z + x.w * y.w;
                }
                hrow[i * (i - 1) / 2 + j] = a;
            }
        }
    }
}

// =====================================================================
// Final layer: out[b] = sigmoid(h2[b,:] . Wt2 + bt2)   (warp per row)
// =====================================================================
__global__ void __launch_bounds__(256) top_final_kernel(
    const float* __restrict__ h2, const float* __restrict__ Wt2,
    const float* __restrict__ bt2, float* __restrict__ out)
{
    const int warp = threadIdx.x >> 5, lane = threadIdx.x & 31;
    const int row = blockIdx.x * 8 + warp;
    const float4* a = (const float4*)(h2 + (size_t)row * 256);
    const float4* w = (const float4*)Wt2;
    float acc = 0.f;
#pragma unroll
    for (int i = 0; i < 2; i++) {
        const float4 x = a[lane * 2 + i], y = w[lane * 2 + i];
        acc += x.x * y.x + x.y * y.y + x.z * y.z + x.w * y.w;
    }
#pragma unroll
    for (int off = 16; off; off >>= 1)
        acc += __shfl_xor_sync(0xffffffffu, acc, off);
    if (lane == 0)
        out[row] = 1.f / (1.f + expf(-(acc + bt2[0])));
}

// =====================================================================
// launch
// =====================================================================
extern "C" void kernel_launch(void* const* d_in, const int* in_sizes, int n_in,
                              void* d_out, int out_size)
{
    const float* dense = (const float*)d_in[0];
    const u64*   sidx  = (const u64*)  d_in[1];
    const float* emb   = (const float*)d_in[2];
    const float* Wb0 = (const float*)d_in[3];  const float* bb0 = (const float*)d_in[4];
    const float* Wb1 = (const float*)d_in[5];  const float* bb1 = (const float*)d_in[6];
    const float* Wb2 = (const float*)d_in[7];  const float* bb2 = (const float*)d_in[8];
    const float* Wt0 = (const float*)d_in[9];  const float* bt0 = (const float*)d_in[10];
    const float* Wt1 = (const float*)d_in[11]; const float* bt1 = (const float*)d_in[12];
    const float* Wt2 = (const float*)d_in[13]; const float* bt2 = (const float*)d_in[14];
    float* out = (float*)d_out;

    float *x0, *x1, *h, *h1, *h2;
    cudaGetSymbolAddress((void**)&x0, g_x0);
    cudaGetSymbolAddress((void**)&x1, g_x1);
    cudaGetSymbolAddress((void**)&h,  g_h);
    cudaGetSymbolAddress((void**)&h1, g_h1);
    cudaGetSymbolAddress((void**)&h2, g_h2);

    // 1) bottom L0: dense -> x0  (16384x512, K=13)
    bot0_kernel<<<BATCH / 32, 256>>>(dense, Wb0, bb0, x0);

    // 2) bottom L1: x0 -> x1  (N=256, K=512)
    gemm_bias_relu<128, 8><<<dim3(256 / 128, BATCH / 128), 256>>>(
        x0, 512, Wb1, bb1, x1, 256, 256, 512, 512 / 16);

    // 3) bottom L2: x1 -> h[:,0:64]  (N=64, K=256), ldc=416
    gemm_bias_relu<64, 4><<<dim3(1, BATCH / 128), 256>>>(
        x1, 256, Wb2, bb2, h, 416, 64, 256, 256 / 16);

    // 4) embedding gather + interaction -> h[:,64:415], zero h[:,415]
    embed_interact_kernel<<<(BATCH + EROWS - 1) / EROWS, 256>>>(sidx, emb, h);

    // 5) top L0: h -> h1  (N=512, K=415, lda=416, 26 K-tiles)
    gemm_bias_relu<128, 8><<<dim3(512 / 128, BATCH / 128), 256>>>(
        h, 416, Wt0, bt0, h1, 512, 512, 415, 26);

    // 6) top L1: h1 -> h2  (N=256, K=512)
    gemm_bias_relu<128, 8><<<dim3(256 / 128, BATCH / 128), 256>>>(
        h1, 512, Wt1, bt1, h2, 256, 256, 512, 512 / 16);

    // 7) final dot + sigmoid
    top_final_kernel<<<BATCH / 8, 256>>>(h2, Wt2, bt2, out);
}

// round 7
// speedup vs baseline: 1.5187x; 1.5187x over previous
#include <cuda_runtime.h>
#include <cuda_bf16.h>
#include <math.h>

#define BATCH   16384
#define NTAB    26
#define VOCABSZ 100000

typedef unsigned long long u64;
typedef unsigned int       u32;
typedef unsigned short     u16;

// ---------------- scratch (bss, zero-initialized, no allocation) --------
__device__ u16   g_x0h[BATCH * 512], g_x0l[BATCH * 512];   // bottom L0 out (split)
__device__ u16   g_x1h[BATCH * 256], g_x1l[BATCH * 256];   // bottom L1 out (split)
__device__ float g_hf [BATCH * 416];                       // fp32 h: [d(64)|inter(351)|z]
__device__ u16   g_hh [BATCH * 448], g_hl [BATCH * 448];   // split h, K-padded to 448
__device__ u16   g_h1h[BATCH * 512], g_h1l[BATCH * 512];   // top L0 out (split)
__device__ float g_h2 [BATCH * 256];                       // top L1 out (fp32)
// transposed + split bf16 weights  (Wt[n][k] = W[k][n]; k >= Kreal zeroed)
__device__ u16 g_Wb1h[256 * 512], g_Wb1l[256 * 512];
__device__ u16 g_Wb2h[ 64 * 256], g_Wb2l[ 64 * 256];
__device__ u16 g_Wt0h[512 * 448], g_Wt0l[512 * 448];
__device__ u16 g_Wt1h[256 * 512], g_Wt1l[256 * 512];

// ---------------- helpers ----------------
__device__ __forceinline__ u32 smem_u32(const void* p) {
    u32 a;
    asm("{ .reg .u64 t; cvta.to.shared.u64 t, %1; cvt.u32.u64 %0, t; }"
        : "=r"(a) : "l"(p));
    return a;
}

// split fp32 pair (a,b) into packed bf16 hi (a->lo half) and bf16 residuals
__device__ __forceinline__ void split2(float a, float b, u32& hi, u32& lo) {
    asm("cvt.rn.bf16x2.f32 %0, %1, %2;" : "=r"(hi) : "f"(b), "f"(a));
    float ra = a - __uint_as_float(hi << 16);
    float rb = b - __uint_as_float(hi & 0xFFFF0000u);
    asm("cvt.rn.bf16x2.f32 %0, %1, %2;" : "=r"(lo) : "f"(rb), "f"(ra));
}

__device__ __forceinline__ void ldmx4(u32* r, u32 addr) {
    asm volatile("ldmatrix.sync.aligned.m8n8.x4.shared.b16 {%0,%1,%2,%3}, [%4];"
                 : "=r"(r[0]), "=r"(r[1]), "=r"(r[2]), "=r"(r[3]) : "r"(addr));
}
__device__ __forceinline__ void mma16816(float* c, const u32* a, const u32* b) {
    asm volatile(
        "mma.sync.aligned.m16n8k16.row.col.f32.bf16.bf16.f32 "
        "{%0,%1,%2,%3}, {%4,%5,%6,%7}, {%8,%9}, {%0,%1,%2,%3};"
        : "+f"(c[0]), "+f"(c[1]), "+f"(c[2]), "+f"(c[3])
        : "r"(a[0]), "r"(a[1]), "r"(a[2]), "r"(a[3]), "r"(b[0]), "r"(b[1]));
}
__device__ __forceinline__ void cp16(u32 dst, const void* src) {
    asm volatile("cp.async.cg.shared.global [%0], [%1], 16;"
                 :: "r"(dst), "l"(__cvta_generic_to_global(src)));
}

// =====================================================================
// Weight prep: Wt_hi/Wt_lo[n*Kpad + k] = split_bf16(W[k*N + n]); k>=Kreal -> 0
// =====================================================================
__global__ void __launch_bounds__(256) prep_w(
    const float* __restrict__ W, int N, int Kreal, int Kpad,
    u16* __restrict__ hi, u16* __restrict__ lo)
{
    const int i = blockIdx.x * 256 + threadIdx.x;
    const int tot = N * (Kpad / 8);
    if (i >= tot) return;
    const int n  = i / (Kpad / 8);
    const int k8 = (i % (Kpad / 8)) * 8;
    u16 hb[8], lb[8];
#pragma unroll
    for (int j = 0; j < 8; j++) {
        const int k = k8 + j;
        const float w = (k < Kreal) ? W[(size_t)k * N + n] : 0.f;
        u32 h, l;
        split2(w, 0.f, h, l);
        hb[j] = (u16)(h & 0xFFFFu);
        lb[j] = (u16)(l & 0xFFFFu);
    }
    *(uint4*)(hi + (size_t)n * Kpad + k8) = *(uint4*)hb;
    *(uint4*)(lo + (size_t)n * Kpad + k8) = *(uint4*)lb;
}

// =====================================================================
// Warp-MMA split-bf16 GEMM: out = relu(A @ Wt^T + bias)
// A: split bf16 [M][Kpad] (hi/lo); Wt: split bf16 [N][Kpad] (hi/lo).
// 3-term: Ah*Bh + Ah*Bl + Al*Bh, fp32 accum (rel err ~1e-5).
// BM=128, BK=32, cp.async double buffer, ldmatrix + mma.m16n8k16.
// Output: SPLIT -> bf16 hi/lo [M][Kout];  else fp32 C [M][ldc].
// =====================================================================
template<int THREADS, int BN, bool SPLIT>
__global__ void __launch_bounds__(THREADS) gemm_mma(
    const u16* __restrict__ Ah, const u16* __restrict__ Al, int Kpad,
    const u16* __restrict__ Bh, const u16* __restrict__ Bl,
    const float* __restrict__ bias,
    float* __restrict__ C, int ldc,
    u16* __restrict__ Oh, u16* __restrict__ Ol, int Kout,
    int NC)
{
    constexpr int SR  = 40;                 // bf16 elems per smem row (80B)
    constexpr int WNC = THREADS / 128;      // n-warp groups (2 or 4)
    constexpr int NW  = BN / WNC;           // cols per warp
    constexpr int NFR = NW / 8;             // n8 frags per warp
    constexpr int SSZ = (256 + 2 * BN) * SR;// bf16 elems per stage
    extern __shared__ u16 sm[];
    const u32 sbase = smem_u32(sm);
    const int tid = threadIdx.x, wid = tid >> 5, lane = tid & 31;
    const int wm = wid & 3, wn = wid >> 2;
    const int bm = blockIdx.y * 128, bn = blockIdx.x * BN;

    float acc[2][NFR][4];
#pragma unroll
    for (int m = 0; m < 2; m++)
#pragma unroll
        for (int n = 0; n < NFR; n++)
#pragma unroll
            for (int j = 0; j < 4; j++) acc[m][n][j] = 0.f;

    auto prefetch = [&](int c, int buf) {
        const u32 sb = sbase + (u32)buf * SSZ * 2;
        constexpr int AOPS = 1024 / THREADS;
#pragma unroll
        for (int i = 0; i < AOPS; i++) {
            const int g = tid + i * THREADS;
            const int arr = g >> 9, r = (g >> 2) & 127, ch = g & 3;
            const u16* src = (arr ? Al : Ah) + (size_t)(bm + r) * Kpad + c * 32 + ch * 8;
            cp16(sb + (u32)(arr * 128 * SR + r * SR + ch * 8) * 2, src);
        }
        constexpr int BOPS = BN * 8 / THREADS;
#pragma unroll
        for (int i = 0; i < BOPS; i++) {
            const int g = tid + i * THREADS;
            const int arr = g / (BN * 4), r = (g >> 2) & (BN - 1), ch = g & 3;
            const u16* src = (arr ? Bl : Bh) + (size_t)(bn + r) * Kpad + c * 32 + ch * 8;
            cp16(sb + (u32)((256 + arr * BN) * SR + r * SR + ch * 8) * 2, src);
        }
    };

    prefetch(0, 0);
    asm volatile("cp.async.commit_group;" ::: "memory");

    for (int c = 0; c < NC; c++) {
        if (c + 1 < NC) prefetch(c + 1, (c + 1) & 1);
        asm volatile("cp.async.commit_group;" ::: "memory");
        asm volatile("cp.async.wait_group 1;" ::: "memory");
        __syncthreads();

        const u32 sA  = sbase + (u32)(c & 1) * SSZ * 2;
        const u32 sBs = sA + 256 * SR * 2;
#pragma unroll
        for (int ks = 0; ks < 2; ks++) {
            u32 ah[2][4], al_[2][4];
#pragma unroll
            for (int mf = 0; mf < 2; mf++) {
                const u32 ra = sA + (u32)(((wm * 32 + mf * 16 + (lane & 15)) * SR
                                           + ks * 16 + (lane >> 4) * 8) * 2);
                ldmx4(ah[mf], ra);
                ldmx4(al_[mf], ra + 128 * SR * 2);
            }
#pragma unroll
            for (int nf2 = 0; nf2 < NFR / 2; nf2++) {
                const u32 rb = sBs + (u32)(((wn * NW + nf2 * 16 + (lane & 7)
                                             + ((lane >> 4) << 3)) * SR
                                            + ks * 16 + ((lane >> 3) & 1) * 8) * 2);
                u32 bh4[4], bl4[4];
                ldmx4(bh4, rb);
                ldmx4(bl4, rb + BN * SR * 2);
#pragma unroll
                for (int hf = 0; hf < 2; hf++) {
                    const int nf = nf2 * 2 + hf;
                    const u32* bh2 = bh4 + hf * 2;
                    const u32* bl2 = bl4 + hf * 2;
#pragma unroll
                    for (int mf = 0; mf < 2; mf++) {
                        mma16816(acc[mf][nf], ah[mf],  bh2);
                        mma16816(acc[mf][nf], ah[mf],  bl2);
                        mma16816(acc[mf][nf], al_[mf], bh2);
                    }
                }
            }
        }
        __syncthreads();
    }

    // ---------------- epilogue: bias + relu + store ----------------
#pragma unroll
    for (int mf = 0; mf < 2; mf++) {
#pragma unroll
        for (int nf = 0; nf < NFR; nf++) {
            const int row0 = bm + wm * 32 + mf * 16 + (lane >> 2);
            const int cc   = bn + wn * NW + nf * 8 + 2 * (lane & 3);
            const float b0 = bias[cc], b1 = bias[cc + 1];
            const float v0 = fmaxf(acc[mf][nf][0] + b0, 0.f);
            const float v1 = fmaxf(acc[mf][nf][1] + b1, 0.f);
            const float v2 = fmaxf(acc[mf][nf][2] + b0, 0.f);
            const float v3 = fmaxf(acc[mf][nf][3] + b1, 0.f);
            if (SPLIT) {
                u32 h, l;
                split2(v0, v1, h, l);
                *(u32*)(Oh + (size_t)row0 * Kout + cc) = h;
                *(u32*)(Ol + (size_t)row0 * Kout + cc) = l;
                split2(v2, v3, h, l);
                *(u32*)(Oh + (size_t)(row0 + 8) * Kout + cc) = h;
                *(u32*)(Ol + (size_t)(row0 + 8) * Kout + cc) = l;
            } else {
                *(float2*)(C + (size_t)row0 * ldc + cc)       = make_float2(v0, v1);
                *(float2*)(C + (size_t)(row0 + 8) * ldc + cc) = make_float2(v2, v3);
            }
        }
    }
}

// =====================================================================
// Bottom MLP layer 0: x0 = relu(dense[16384,13] @ Wb0 + bb0), split-bf16 out
// =====================================================================
__global__ void __launch_bounds__(256) bot0_kernel(
    const float* __restrict__ dense, const float* __restrict__ W,
    const float* __restrict__ bias, u16* __restrict__ xh, u16* __restrict__ xl)
{
    __shared__ float sW[13 * 512];
    __shared__ float sB[512];
    __shared__ float sD[32 * 13];
    const int tid = threadIdx.x;
    const int rbase = blockIdx.x * 32;

    for (int i = tid; i < 13 * 512; i += 256) sW[i] = W[i];
    for (int i = tid; i < 512;      i += 256) sB[i] = bias[i];
    for (int i = tid; i < 32 * 13;  i += 256) sD[i] = dense[(size_t)rbase * 13 + i];
    __syncthreads();

    const int q  = tid & 127;
    const int rs = tid >> 7;
    const int c0 = q * 4;

    float4 w[13];
#pragma unroll
    for (int k = 0; k < 13; k++) w[k] = *(const float4*)&sW[k * 512 + c0];
    const float4 bq = *(const float4*)&sB[c0];

    for (int rr = 0; rr < 16; rr++) {
        const int r = rs * 16 + rr;
        float4 acc = bq;
#pragma unroll
        for (int k = 0; k < 13; k++) {
            const float a = sD[r * 13 + k];
            acc.x += a * w[k].x; acc.y += a * w[k].y;
            acc.z += a * w[k].z; acc.w += a * w[k].w;
        }
        acc.x = fmaxf(acc.x, 0.f); acc.y = fmaxf(acc.y, 0.f);
        acc.z = fmaxf(acc.z, 0.f); acc.w = fmaxf(acc.w, 0.f);
        u32 h0, l0, h1, l1;
        split2(acc.x, acc.y, h0, l0);
        split2(acc.z, acc.w, h1, l1);
        const size_t o = (size_t)(rbase + r) * 512 + c0;
        *(uint2*)(xh + o) = make_uint2(h0, h1);
        *(uint2*)(xl + o) = make_uint2(l0, l1);
    }
}

// =====================================================================
// Embedding gather + pairwise interaction (R4-proven, unchanged; fp32 h)
// =====================================================================
#define EROWS 6
#define VSTR  68

__global__ void __launch_bounds__(256) embed_interact_kernel(
    const u64* __restrict__ sidx, const float* __restrict__ emb,
    float* __restrict__ h)
{
    __shared__ float T[EROWS * 28 * VSTR];
    __shared__ int s_is32;
    const int tid = threadIdx.x;
    const int rbase = blockIdx.x * EROWS;

    if (tid == 0) {
        int f = 0;
#pragma unroll
        for (int i = 0; i < 16; i++)
            if (sidx[i] >> 32) f = 1;
        s_is32 = f;
    }
    __syncthreads();
    const bool is32 = (s_is32 != 0);
    const int* sidx32 = (const int*)sidx;

    float4* T4 = (float4*)T;

    for (int u = tid; u < EROWS * 26 * 16; u += 256) {
        const int v = u >> 4, f = u & 15;
        const int r = v / 26, t = v - r * 26;
        const int grow = rbase + r;
        if (grow < BATCH) {
            long long idx;
            if (is32) idx = (long long)sidx32[grow * 26 + t];
            else      idx = (long long)sidx[grow * 26 + t];
            const float4* src =
                (const float4*)(emb + ((size_t)t * VOCABSZ + (size_t)idx) * 64);
            T4[(r * 28 + t) * 17 + f] = src[f];
        }
    }
    for (int u = tid; u < EROWS * 16; u += 256) {
        const int r = u >> 4, f = u & 15;
        const int grow = rbase + r;
        if (grow < BATCH)
            T4[(r * 28 + 26) * 17 + f] = *(const float4*)(h + (size_t)grow * 416 + f * 4);
        T4[(r * 28 + 27) * 17 + f] = make_float4(0.f, 0.f, 0.f, 0.f);
    }
    if (tid < EROWS) {
        const int grow = rbase + tid;
        if (grow < BATCH) h[(size_t)grow * 416 + 415] = 0.f;
    }
    __syncthreads();

    for (int task = tid; task < EROWS * 105; task += 256) {
        const int r = task / 105, tt = task - r * 105;
        const int grow = rbase + r;
        if (grow >= BATCH) continue;
        float* hrow = h + (size_t)grow * 416 + 64;
        const float4* base = (const float4*)T + (size_t)r * 28 * 17;

        if (tt < 91) {
            int ti = 1;
            while ((ti * (ti + 1)) / 2 <= tt) ti++;
            const int tj = tt - ti * (ti - 1) / 2;
            const int i0 = 2 * ti, i1 = i0 + 1, j0 = 2 * tj, j1 = j0 + 1;
            const float4* Ti0 = base + i0 * 17;
            const float4* Ti1 = base + i1 * 17;
            const float4* Tj0 = base + j0 * 17;
            const float4* Tj1 = base + j1 * 17;
            float a00 = 0.f, a01 = 0.f, a10 = 0.f, a11 = 0.f;
#pragma unroll
            for (int f = 0; f < 16; f++) {
                const float4 x0 = Ti0[f], x1 = Ti1[f];
                const float4 y0 = Tj0[f], y1 = Tj1[f];
                a00 += x0.x * y0.x + x0.y * y0.y + x0.z * y0.z + x0.w * y0.w;
                a01 += x0.x * y1.x + x0.y * y1.y + x0.z * y1.z + x0.w * y1.w;
                a10 += x1.x * y0.x + x1.y * y0.y + x1.z * y0.z + x1.w * y0.w;
                a11 += x1.x * y1.x + x1.y * y1.y + x1.z * y1.z + x1.w * y1.w;
            }
            hrow[i0 * (i0 - 1) / 2 + j0] = a00;
            hrow[i0 * (i0 - 1) / 2 + j1] = a01;
            if (i1 < 27) {
                hrow[i1 * (i1 - 1) / 2 + j0] = a10;
                hrow[i1 * (i1 - 1) / 2 + j1] = a11;
            }
        } else {
            const int ti = tt - 91;
            const int i = 2 * ti + 1, j = 2 * ti;
            if (i < 27) {
                const float4* Ti = base + i * 17;
                const float4* Tj = base + j * 17;
                float a = 0.f;
#pragma unroll
                for (int f = 0; f < 16; f++) {
                    const float4 x = Ti[f], y = Tj[f];
                    a += x.x * y.x + x.y * y.y + x.z * y.z + x.w * y.w;
                }
                hrow[i * (i - 1) / 2 + j] = a;
            }
        }
    }
}

// =====================================================================
// h fp32 [16384][416] -> split bf16 [16384][448] (pad cols stay bss-zero)
// =====================================================================
__global__ void __launch_bounds__(256) split_h_kernel(
    const float* __restrict__ h, u16* __restrict__ hh, u16* __restrict__ hl)
{
    const int i = blockIdx.x * 256 + threadIdx.x;       // over 16384*104 float4s
    if (i >= BATCH * 104) return;
    const int r = i / 104, c4 = i % 104;
    const float4 v = *(const float4*)(h + (size_t)r * 416 + c4 * 4);
    u32 h0, l0, h1, l1;
    split2(v.x, v.y, h0, l0);
    split2(v.z, v.w, h1, l1);
    const size_t o = (size_t)r * 448 + c4 * 4;
    *(uint2*)(hh + o) = make_uint2(h0, h1);
    *(uint2*)(hl + o) = make_uint2(l0, l1);
}

// =====================================================================
// Final layer: out[b] = sigmoid(h2[b,:] . Wt2 + bt2)
// =====================================================================
__global__ void __launch_bounds__(256) top_final_kernel(
    const float* __restrict__ h2, const float* __restrict__ Wt2,
    const float* __restrict__ bt2, float* __restrict__ out)
{
    const int warp = threadIdx.x >> 5, lane = threadIdx.x & 31;
    const int row = blockIdx.x * 8 + warp;
    const float4* a = (const float4*)(h2 + (size_t)row * 256);
    const float4* w = (const float4*)Wt2;
    float acc = 0.f;
#pragma unroll
    for (int i = 0; i < 2; i++) {
        const float4 x = a[lane * 2 + i], y = w[lane * 2 + i];
        acc += x.x * y.x + x.y * y.y + x.z * y.z + x.w * y.w;
    }
#pragma unroll
    for (int off = 16; off; off >>= 1)
        acc += __shfl_xor_sync(0xffffffffu, acc, off);
    if (lane == 0)
        out[row] = 1.f / (1.f + expf(-(acc + bt2[0])));
}

// =====================================================================
// launch
// =====================================================================
extern "C" void kernel_launch(void* const* d_in, const int* in_sizes, int n_in,
                              void* d_out, int out_size)
{
    const float* dense = (const float*)d_in[0];
    const u64*   sidx  = (const u64*)  d_in[1];
    const float* emb   = (const float*)d_in[2];
    const float* Wb0 = (const float*)d_in[3];  const float* bb0 = (const float*)d_in[4];
    const float* Wb1 = (const float*)d_in[5];  const float* bb1 = (const float*)d_in[6];
    const float* Wb2 = (const float*)d_in[7];  const float* bb2 = (const float*)d_in[8];
    const float* Wt0 = (const float*)d_in[9];  const float* bt0 = (const float*)d_in[10];
    const float* Wt1 = (const float*)d_in[11]; const float* bt1 = (const float*)d_in[12];
    const float* Wt2 = (const float*)d_in[13]; const float* bt2 = (const float*)d_in[14];
    float* out = (float*)d_out;

    u16 *x0h, *x0l, *x1h, *x1l, *hh, *hl, *h1h, *h1l;
    float *hf, *h2;
    cudaGetSymbolAddress((void**)&x0h, g_x0h); cudaGetSymbolAddress((void**)&x0l, g_x0l);
    cudaGetSymbolAddress((void**)&x1h, g_x1h); cudaGetSymbolAddress((void**)&x1l, g_x1l);
    cudaGetSymbolAddress((void**)&hf,  g_hf);
    cudaGetSymbolAddress((void**)&hh,  g_hh);  cudaGetSymbolAddress((void**)&hl,  g_hl);
    cudaGetSymbolAddress((void**)&h1h, g_h1h); cudaGetSymbolAddress((void**)&h1l, g_h1l);
    cudaGetSymbolAddress((void**)&h2,  g_h2);
    u16 *wb1h, *wb1l, *wb2h, *wb2l, *wt0h, *wt0l, *wt1h, *wt1l;
    cudaGetSymbolAddress((void**)&wb1h, g_Wb1h); cudaGetSymbolAddress((void**)&wb1l, g_Wb1l);
    cudaGetSymbolAddress((void**)&wb2h, g_Wb2h); cudaGetSymbolAddress((void**)&wb2l, g_Wb2l);
    cudaGetSymbolAddress((void**)&wt0h, g_Wt0h); cudaGetSymbolAddress((void**)&wt0l, g_Wt0l);
    cudaGetSymbolAddress((void**)&wt1h, g_Wt1h); cudaGetSymbolAddress((void**)&wt1l, g_Wt1l);

    // dynamic smem opt-in (idempotent, non-stream API: capture-safe)
    const int SM256 = 2 * (256 + 2 * 256) * 40 * 2;   // 122,880 B
    const int SM64  = 2 * (256 + 2 *  64) * 40 * 2;   //  61,440 B
    cudaFuncSetAttribute((const void*)gemm_mma<512, 256, true>,
                         cudaFuncAttributeMaxDynamicSharedMemorySize, SM256);
    cudaFuncSetAttribute((const void*)gemm_mma<512, 256, false>,
                         cudaFuncAttributeMaxDynamicSharedMemorySize, SM256);
    cudaFuncSetAttribute((const void*)gemm_mma<256, 64, false>,
                         cudaFuncAttributeMaxDynamicSharedMemorySize, SM64);

    // 0) weight transpose + bf16 split (zero-padded K)
    prep_w<<<(256 * 512 / 8 + 255) / 256, 256>>>(Wb1, 256, 512, 512, wb1h, wb1l);
    prep_w<<<( 64 * 256 / 8 + 255) / 256, 256>>>(Wb2,  64, 256, 256, wb2h, wb2l);
    prep_w<<<(512 * 448 / 8 + 255) / 256, 256>>>(Wt0, 512, 415, 448, wt0h, wt0l);
    prep_w<<<(256 * 512 / 8 + 255) / 256, 256>>>(Wt1, 256, 512, 512, wt1h, wt1l);

    // 1) bottom L0: dense -> x0 (split)
    bot0_kernel<<<BATCH / 32, 256>>>(dense, Wb0, bb0, x0h, x0l);

    // 2) bottom L1: x0 -> x1 (split out)  N=256 K=512
    gemm_mma<512, 256, true><<<dim3(1, BATCH / 128), 512, SM256>>>(
        x0h, x0l, 512, wb1h, wb1l, bb1, nullptr, 0, x1h, x1l, 256, 16);

    // 3) bottom L2: x1 -> hf[:,0:64] (fp32, ldc=416)  N=64 K=256
    gemm_mma<256, 64, false><<<dim3(1, BATCH / 128), 256, SM64>>>(
        x1h, x1l, 256, wb2h, wb2l, bb2, hf, 416, nullptr, nullptr, 0, 8);

    // 4) embedding gather + interaction -> hf[:,64:415], zero hf[:,415]
    embed_interact_kernel<<<(BATCH + EROWS - 1) / EROWS, 256>>>(sidx, emb, hf);

    // 5) split hf -> hh/hl [16384][448]
    split_h_kernel<<<(BATCH * 104 + 255) / 256, 256>>>(hf, hh, hl);

    // 6) top L0: h -> h1 (split out)  N=512 K=448
    gemm_mma<512, 256, true><<<dim3(2, BATCH / 128), 512, SM256>>>(
        hh, hl, 448, wt0h, wt0l, bt0, nullptr, 0, h1h, h1l, 512, 14);

    // 7) top L1: h1 -> h2 (fp32)  N=256 K=512
    gemm_mma<512, 256, false><<<dim3(1, BATCH / 128), 512, SM256>>>(
        h1h, h1l, 512, wt1h, wt1l, bt1, h2, 256, nullptr, nullptr, 0, 16);

    // 8) final dot + sigmoid
    top_final_kernel<<<BATCH / 8, 256>>>(h2, Wt2, bt2, out);
}

// round 8
// speedup vs baseline: 1.5917x; 1.0480x over previous
#include <cuda_runtime.h>
#include <cuda_bf16.h>
#include <math.h>

#define BATCH   16384
#define NTAB    26
#define VOCABSZ 100000

typedef unsigned long long u64;
typedef unsigned int       u32;
typedef unsigned short     u16;

// ---------------- scratch (bss, zero-initialized, no allocation) --------
__device__ u16   g_x0h[BATCH * 512], g_x0l[BATCH * 512];   // bottom L0 out (split)
__device__ u16   g_x1h[BATCH * 256], g_x1l[BATCH * 256];   // bottom L1 out (split)
__device__ float g_d  [BATCH * 64];                        // bottom L2 out (fp32 d)
__device__ u16   g_hh [BATCH * 448], g_hl [BATCH * 448];   // split h (d|inter|zero pad)
__device__ u16   g_h1h[BATCH * 512], g_h1l[BATCH * 512];   // top L0 out (split)
__device__ float g_h2 [BATCH * 256];                       // top L1 out (fp32)
// transposed + split bf16 weights  (Wt[n][k] = W[k][n]; k >= Kreal zeroed)
__device__ u16 g_Wb1h[256 * 512], g_Wb1l[256 * 512];
__device__ u16 g_Wb2h[ 64 * 256], g_Wb2l[ 64 * 256];
__device__ u16 g_Wt0h[512 * 448], g_Wt0l[512 * 448];
__device__ u16 g_Wt1h[256 * 512], g_Wt1l[256 * 512];

// ---------------- helpers ----------------
__device__ __forceinline__ u32 smem_u32(const void* p) {
    u32 a;
    asm("{ .reg .u64 t; cvta.to.shared.u64 t, %1; cvt.u32.u64 %0, t; }"
        : "=r"(a) : "l"(p));
    return a;
}

// split fp32 pair (a,b) into packed bf16 hi (a->lo half) and bf16 residuals
__device__ __forceinline__ void split2(float a, float b, u32& hi, u32& lo) {
    asm("cvt.rn.bf16x2.f32 %0, %1, %2;" : "=r"(hi) : "f"(b), "f"(a));
    float ra = a - __uint_as_float(hi << 16);
    float rb = b - __uint_as_float(hi & 0xFFFF0000u);
    asm("cvt.rn.bf16x2.f32 %0, %1, %2;" : "=r"(lo) : "f"(rb), "f"(ra));
}

__device__ __forceinline__ void ldmx4(u32* r, u32 addr) {
    asm volatile("ldmatrix.sync.aligned.m8n8.x4.shared.b16 {%0,%1,%2,%3}, [%4];"
                 : "=r"(r[0]), "=r"(r[1]), "=r"(r[2]), "=r"(r[3]) : "r"(addr));
}
__device__ __forceinline__ void mma16816(float* c, const u32* a, const u32* b) {
    asm volatile(
        "mma.sync.aligned.m16n8k16.row.col.f32.bf16.bf16.f32 "
        "{%0,%1,%2,%3}, {%4,%5,%6,%7}, {%8,%9}, {%0,%1,%2,%3};"
        : "+f"(c[0]), "+f"(c[1]), "+f"(c[2]), "+f"(c[3])
        : "r"(a[0]), "r"(a[1]), "r"(a[2]), "r"(a[3]), "r"(b[0]), "r"(b[1]));
}
__device__ __forceinline__ void cp16(u32 dst, const void* src) {
    asm volatile("cp.async.cg.shared.global [%0], [%1], 16;"
                 :: "r"(dst), "l"(__cvta_generic_to_global(src)));
}

// =====================================================================
// Weight prep (single launch): all 4 weights transposed + split.
// =====================================================================
__global__ void __launch_bounds__(256) prep_all(
    const float* __restrict__ Wb1, const float* __restrict__ Wb2,
    const float* __restrict__ Wt0, const float* __restrict__ Wt1,
    u16* __restrict__ b1h, u16* __restrict__ b1l,
    u16* __restrict__ b2h, u16* __restrict__ b2l,
    u16* __restrict__ t0h, u16* __restrict__ t0l,
    u16* __restrict__ t1h, u16* __restrict__ t1l)
{
    const int i = blockIdx.x * 256 + threadIdx.x;
    const float* W; u16 *H, *L; int N, Kreal, Kpad, li;
    if (i < 16384)      { W = Wb1; H = b1h; L = b1l; N = 256; Kreal = 512; Kpad = 512; li = i; }
    else if (i < 18432) { W = Wb2; H = b2h; L = b2l; N =  64; Kreal = 256; Kpad = 256; li = i - 16384; }
    else if (i < 47104) { W = Wt0; H = t0h; L = t0l; N = 512; Kreal = 415; Kpad = 448; li = i - 18432; }
    else if (i < 63488) { W = Wt1; H = t1h; L = t1l; N = 256; Kreal = 512; Kpad = 512; li = i - 47104; }
    else return;
    const int n  = li / (Kpad / 8);
    const int k8 = (li % (Kpad / 8)) * 8;
    u16 hb[8], lb[8];
#pragma unroll
    for (int j = 0; j < 8; j++) {
        const int k = k8 + j;
        const float w = (k < Kreal) ? W[(size_t)k * N + n] : 0.f;
        u32 h, l;
        split2(w, 0.f, h, l);
        hb[j] = (u16)(h & 0xFFFFu);
        lb[j] = (u16)(l & 0xFFFFu);
    }
    *(uint4*)(H + (size_t)n * Kpad + k8) = *(uint4*)hb;
    *(uint4*)(L + (size_t)n * Kpad + k8) = *(uint4*)lb;
}

// =====================================================================
// Warp-MMA split-bf16 GEMM: out = relu(A @ Wt^T + bias)
// 3-term: Ah*Bh + Ah*Bl + Al*Bh, fp32 accum. BM=128, BK=32,
// 3-stage cp.async pipeline, ldmatrix + mma.m16n8k16.
// OMODE: 0 = fp32 C;  1 = split bf16 Oh/Ol;  2 = both.
// =====================================================================
template<int THREADS, int BN, int OMODE>
__global__ void __launch_bounds__(THREADS) gemm_mma(
    const u16* __restrict__ Ah, const u16* __restrict__ Al, int Kpad,
    const u16* __restrict__ Bh, const u16* __restrict__ Bl,
    const float* __restrict__ bias,
    float* __restrict__ C, int ldc,
    u16* __restrict__ Oh, u16* __restrict__ Ol, int Kout,
    int NC)
{
    constexpr int SR  = 40;                 // bf16 elems per smem row (80B)
    constexpr int WNC = THREADS / 128;      // n-warp groups
    constexpr int NW  = BN / WNC;           // cols per warp
    constexpr int NFR = NW / 8;             // n8 frags per warp
    constexpr int SSZ = (256 + 2 * BN) * SR;// bf16 elems per stage
    extern __shared__ u16 sm[];
    const u32 sbase = smem_u32(sm);
    const int tid = threadIdx.x, wid = tid >> 5, lane = tid & 31;
    const int wm = wid & 3, wn = wid >> 2;
    const int bm = blockIdx.y * 128, bn = blockIdx.x * BN;

    float acc[2][NFR][4];
#pragma unroll
    for (int m = 0; m < 2; m++)
#pragma unroll
        for (int n = 0; n < NFR; n++)
#pragma unroll
            for (int j = 0; j < 4; j++) acc[m][n][j] = 0.f;

    auto prefetch = [&](int c, int buf) {
        const u32 sb = sbase + (u32)buf * SSZ * 2;
        constexpr int AOPS = 1024 / THREADS;
#pragma unroll
        for (int i = 0; i < AOPS; i++) {
            const int g = tid + i * THREADS;
            const int arr = g >> 9, r = (g >> 2) & 127, ch = g & 3;
            const u16* src = (arr ? Al : Ah) + (size_t)(bm + r) * Kpad + c * 32 + ch * 8;
            cp16(sb + (u32)(arr * 128 * SR + r * SR + ch * 8) * 2, src);
        }
        constexpr int BOPS = BN * 8 / THREADS;
#pragma unroll
        for (int i = 0; i < BOPS; i++) {
            const int g = tid + i * THREADS;
            const int arr = g / (BN * 4), r = (g >> 2) & (BN - 1), ch = g & 3;
            const u16* src = (arr ? Bl : Bh) + (size_t)(bn + r) * Kpad + c * 32 + ch * 8;
            cp16(sb + (u32)((256 + arr * BN) * SR + r * SR + ch * 8) * 2, src);
        }
    };

    prefetch(0, 0);
    asm volatile("cp.async.commit_group;" ::: "memory");
    if (NC > 1) prefetch(1, 1);
    asm volatile("cp.async.commit_group;" ::: "memory");

    for (int c = 0; c < NC; c++) {
        asm volatile("cp.async.wait_group 1;" ::: "memory");
        __syncthreads();
        if (c + 2 < NC) prefetch(c + 2, (c + 2) % 3);
        asm volatile("cp.async.commit_group;" ::: "memory");

        const u32 sA  = sbase + (u32)(c % 3) * SSZ * 2;
        const u32 sBs = sA + 256 * SR * 2;
#pragma unroll
        for (int ks = 0; ks < 2; ks++) {
            u32 ah[2][4], al_[2][4];
#pragma unroll
            for (int mf = 0; mf < 2; mf++) {
                const u32 ra = sA + (u32)(((wm * 32 + mf * 16 + (lane & 15)) * SR
                                           + ks * 16 + (lane >> 4) * 8) * 2);
                ldmx4(ah[mf], ra);
                ldmx4(al_[mf], ra + 128 * SR * 2);
            }
#pragma unroll
            for (int nf2 = 0; nf2 < NFR / 2; nf2++) {
                const u32 rb = sBs + (u32)(((wn * NW + nf2 * 16 + (lane & 7)
                                             + ((lane >> 4) << 3)) * SR
                                            + ks * 16 + ((lane >> 3) & 1) * 8) * 2);
                u32 bh4[4], bl4[4];
                ldmx4(bh4, rb);
                ldmx4(bl4, rb + BN * SR * 2);
#pragma unroll
                for (int hf = 0; hf < 2; hf++) {
                    const int nf = nf2 * 2 + hf;
                    const u32* bh2 = bh4 + hf * 2;
                    const u32* bl2 = bl4 + hf * 2;
#pragma unroll
                    for (int mf = 0; mf < 2; mf++) {
                        mma16816(acc[mf][nf], ah[mf],  bh2);
                        mma16816(acc[mf][nf], ah[mf],  bl2);
                        mma16816(acc[mf][nf], al_[mf], bh2);
                    }
                }
            }
        }
        __syncthreads();
    }

    // ---------------- epilogue: bias + relu + store ----------------
#pragma unroll
    for (int mf = 0; mf < 2; mf++) {
#pragma unroll
        for (int nf = 0; nf < NFR; nf++) {
            const int row0 = bm + wm * 32 + mf * 16 + (lane >> 2);
            const int cc   = bn + wn * NW + nf * 8 + 2 * (lane & 3);
            const float b0 = bias[cc], b1 = bias[cc + 1];
            const float v0 = fmaxf(acc[mf][nf][0] + b0, 0.f);
            const float v1 = fmaxf(acc[mf][nf][1] + b1, 0.f);
            const float v2 = fmaxf(acc[mf][nf][2] + b0, 0.f);
            const float v3 = fmaxf(acc[mf][nf][3] + b1, 0.f);
            if (OMODE != 1) {
                *(float2*)(C + (size_t)row0 * ldc + cc)       = make_float2(v0, v1);
                *(float2*)(C + (size_t)(row0 + 8) * ldc + cc) = make_float2(v2, v3);
            }
            if (OMODE != 0) {
                u32 h, l;
                split2(v0, v1, h, l);
                *(u32*)(Oh + (size_t)row0 * Kout + cc) = h;
                *(u32*)(Ol + (size_t)row0 * Kout + cc) = l;
                split2(v2, v3, h, l);
                *(u32*)(Oh + (size_t)(row0 + 8) * Kout + cc) = h;
                *(u32*)(Ol + (size_t)(row0 + 8) * Kout + cc) = l;
            }
        }
    }
}

// =====================================================================
// Bottom MLP layer 0: x0 = relu(dense[16384,13] @ Wb0 + bb0), split-bf16 out
// =====================================================================
__global__ void __launch_bounds__(256) bot0_kernel(
    const float* __restrict__ dense, const float* __restrict__ W,
    const float* __restrict__ bias, u16* __restrict__ xh, u16* __restrict__ xl)
{
    __shared__ float sW[13 * 512];
    __shared__ float sB[512];
    __shared__ float sD[32 * 13];
    const int tid = threadIdx.x;
    const int rbase = blockIdx.x * 32;

    for (int i = tid; i < 13 * 512; i += 256) sW[i] = W[i];
    for (int i = tid; i < 512;      i += 256) sB[i] = bias[i];
    for (int i = tid; i < 32 * 13;  i += 256) sD[i] = dense[(size_t)rbase * 13 + i];
    __syncthreads();

    const int q  = tid & 127;
    const int rs = tid >> 7;
    const int c0 = q * 4;

    float4 w[13];
#pragma unroll
    for (int k = 0; k < 13; k++) w[k] = *(const float4*)&sW[k * 512 + c0];
    const float4 bq = *(const float4*)&sB[c0];

    for (int rr = 0; rr < 16; rr++) {
        const int r = rs * 16 + rr;
        float4 acc = bq;
#pragma unroll
        for (int k = 0; k < 13; k++) {
            const float a = sD[r * 13 + k];
            acc.x += a * w[k].x; acc.y += a * w[k].y;
            acc.z += a * w[k].z; acc.w += a * w[k].w;
        }
        acc.x = fmaxf(acc.x, 0.f); acc.y = fmaxf(acc.y, 0.f);
        acc.z = fmaxf(acc.z, 0.f); acc.w = fmaxf(acc.w, 0.f);
        u32 h0, l0, h1, l1;
        split2(acc.x, acc.y, h0, l0);
        split2(acc.z, acc.w, h1, l1);
        const size_t o = (size_t)(rbase + r) * 512 + c0;
        *(uint2*)(xh + o) = make_uint2(h0, h1);
        *(uint2*)(xl + o) = make_uint2(l0, l1);
    }
}

// =====================================================================
// Embedding gather + pairwise interaction, 4x4 vector tiles,
// split-bf16 output written directly into hh/hl (cols 64..414).
// T layout: [EROWS][28 vectors][stride 17 float4]; vec 26 = d, vec 27 = 0.
// =====================================================================
#define EROWS 8

__global__ void __launch_bounds__(256) embed_interact2(
    const u64* __restrict__ sidx, const float* __restrict__ emb,
    const float* __restrict__ dvec,
    u16* __restrict__ hh, u16* __restrict__ hl)
{
    extern __shared__ float Tsh[];
    __shared__ int s_is32;
    float4* T4 = (float4*)Tsh;
    const u32 sbase = smem_u32(Tsh);
    const int tid = threadIdx.x;
    const int rbase = blockIdx.x * EROWS;     // BATCH % EROWS == 0

    if (tid == 0) {
        int f = 0;
#pragma unroll
        for (int i = 0; i < 16; i++)
            if (sidx[i] >> 32) f = 1;         // int64 indices have hi word = 0
        s_is32 = f;
    }
    __syncthreads();
    const bool is32 = (s_is32 != 0);
    const int* sidx32 = (const int*)sidx;

    // gather embeddings via cp.async: EROWS*26 vectors x 16 float4
    for (int u = tid; u < EROWS * 26 * 16; u += 256) {
        const int v = u >> 4, f = u & 15;
        const int r = v / 26, t = v - r * 26;
        const int grow = rbase + r;
        long long idx;
        if (is32) idx = (long long)sidx32[grow * 26 + t];
        else      idx = (long long)sidx[grow * 26 + t];
        const float* src = emb + ((size_t)t * VOCABSZ + (size_t)idx) * 64 + f * 4;
        cp16(sbase + (u32)(((r * 28 + t) * 17 + f) * 16), src);
    }
    // d vector (vec 26) via cp.async; zero pad (vec 27) via plain store
    for (int u = tid; u < EROWS * 16; u += 256) {
        const int r = u >> 4, f = u & 15;
        cp16(sbase + (u32)(((r * 28 + 26) * 17 + f) * 16),
             dvec + (size_t)(rbase + r) * 64 + f * 4);
        T4[(r * 28 + 27) * 17 + f] = make_float4(0.f, 0.f, 0.f, 0.f);
    }
    asm volatile("cp.async.commit_group;" ::: "memory");
    asm volatile("cp.async.wait_group 0;" ::: "memory");
    __syncthreads();

    // tasks: per row 21 full 4x4 tiles + 7 diagonal tiles = 28
    const int task = tid;
    if (task < EROWS * 28) {
        const int r = task / 28, tt = task - r * 28;
        const int grow = rbase + r;
        u16* hrh = hh + (size_t)grow * 448 + 64;
        u16* hrl = hl + (size_t)grow * 448 + 64;
        const float4* bb = T4 + (size_t)r * 28 * 17;

        if (tt < 21) {                        // full tile: ti in 1..6, tj < ti
            int ti = 1;
            while ((ti * (ti + 1)) / 2 <= tt) ti++;
            const int tj = tt - ti * (ti - 1) / 2;
            const float4* Ti = bb + (4 * ti) * 17;
            const float4* Tj = bb + (4 * tj) * 17;
            float a[4][4];
#pragma unroll
            for (int ii = 0; ii < 4; ii++)
#pragma unroll
                for (int jj = 0; jj < 4; jj++) a[ii][jj] = 0.f;
#pragma unroll
            for (int f = 0; f < 16; f++) {
                float4 x[4], y[4];
#pragma unroll
                for (int ii = 0; ii < 4; ii++) x[ii] = Ti[ii * 17 + f];
#pragma unroll
                for (int jj = 0; jj < 4; jj++) y[jj] = Tj[jj * 17 + f];
#pragma unroll
                for (int ii = 0; ii < 4; ii++)
#pragma unroll
                    for (int jj = 0; jj < 4; jj++)
                        a[ii][jj] += x[ii].x * y[jj].x + x[ii].y * y[jj].y
                                   + x[ii].z * y[jj].z + x[ii].w * y[jj].w;
            }
#pragma unroll
            for (int ii = 0; ii < 4; ii++) {
                const int i = 4 * ti + ii;
                if (i < 27) {
                    const int base_i = i * (i - 1) / 2;
#pragma unroll
                    for (int jj = 0; jj < 4; jj++) {
                        const int j = 4 * tj + jj;
                        u32 h, l;
                        split2(a[ii][jj], 0.f, h, l);
                        hrh[base_i + j] = (u16)h;
                        hrl[base_i + j] = (u16)l;
                    }
                }
            }
        } else {                              // diagonal tile: 6 pairs within 4
            const int ti = tt - 21;
            const float4* Ti = bb + (4 * ti) * 17;
            float a[6];
#pragma unroll
            for (int p = 0; p < 6; p++) a[p] = 0.f;
#pragma unroll
            for (int f = 0; f < 16; f++) {
                float4 x[4];
#pragma unroll
                for (int ii = 0; ii < 4; ii++) x[ii] = Ti[ii * 17 + f];
                a[0] += x[1].x * x[0].x + x[1].y * x[0].y + x[1].z * x[0].z + x[1].w * x[0].w;
                a[1] += x[2].x * x[0].x + x[2].y * x[0].y + x[2].z * x[0].z + x[2].w * x[0].w;
                a[2] += x[2].x * x[1].x + x[2].y * x[1].y + x[2].z * x[1].z + x[2].w * x[1].w;
                a[3] += x[3].x * x[0].x + x[3].y * x[0].y + x[3].z * x[0].z + x[3].w * x[0].w;
                a[4] += x[3].x * x[1].x + x[3].y * x[1].y + x[3].z * x[1].z + x[3].w * x[1].w;
                a[5] += x[3].x * x[2].x + x[3].y * x[2].y + x[3].z * x[2].z + x[3].w * x[2].w;
            }
            const int pi[6] = {1, 2, 2, 3, 3, 3};
            const int pj[6] = {0, 0, 1, 0, 1, 2};
#pragma unroll
            for (int p = 0; p < 6; p++) {
                const int i = 4 * ti + pi[p], j = 4 * ti + pj[p];
                if (i < 27) {
                    u32 h, l;
                    split2(a[p], 0.f, h, l);
                    hrh[i * (i - 1) / 2 + j] = (u16)h;
                    hrl[i * (i - 1) / 2 + j] = (u16)l;
                }
            }
        }
    }
}

// =====================================================================
// Final layer: out[b] = sigmoid(h2[b,:] . Wt2 + bt2)
// =====================================================================
__global__ void __launch_bounds__(256) top_final_kernel(
    const float* __restrict__ h2, const float* __restrict__ Wt2,
    const float* __restrict__ bt2, float* __restrict__ out)
{
    const int warp = threadIdx.x >> 5, lane = threadIdx.x & 31;
    const int row = blockIdx.x * 8 + warp;
    const float4* a = (const float4*)(h2 + (size_t)row * 256);
    const float4* w = (const float4*)Wt2;
    float acc = 0.f;
#pragma unroll
    for (int i = 0; i < 2; i++) {
        const float4 x = a[lane * 2 + i], y = w[lane * 2 + i];
        acc += x.x * y.x + x.y * y.y + x.z * y.z + x.w * y.w;
    }
#pragma unroll
    for (int off = 16; off; off >>= 1)
        acc += __shfl_xor_sync(0xffffffffu, acc, off);
    if (lane == 0)
        out[row] = 1.f / (1.f + expf(-(acc + bt2[0])));
}

// =====================================================================
// launch
// =====================================================================
extern "C" void kernel_launch(void* const* d_in, const int* in_sizes, int n_in,
                              void* d_out, int out_size)
{
    const float* dense = (const float*)d_in[0];
    const u64*   sidx  = (const u64*)  d_in[1];
    const float* emb   = (const float*)d_in[2];
    const float* Wb0 = (const float*)d_in[3];  const float* bb0 = (const float*)d_in[4];
    const float* Wb1 = (const float*)d_in[5];  const float* bb1 = (const float*)d_in[6];
    const float* Wb2 = (const float*)d_in[7];  const float* bb2 = (const float*)d_in[8];
    const float* Wt0 = (const float*)d_in[9];  const float* bt0 = (const float*)d_in[10];
    const float* Wt1 = (const float*)d_in[11]; const float* bt1 = (const float*)d_in[12];
    const float* Wt2 = (const float*)d_in[13]; const float* bt2 = (const float*)d_in[14];
    float* out = (float*)d_out;

    u16 *x0h, *x0l, *x1h, *x1l, *hh, *hl, *h1h, *h1l;
    float *dv, *h2;
    cudaGetSymbolAddress((void**)&x0h, g_x0h); cudaGetSymbolAddress((void**)&x0l, g_x0l);
    cudaGetSymbolAddress((void**)&x1h, g_x1h); cudaGetSymbolAddress((void**)&x1l, g_x1l);
    cudaGetSymbolAddress((void**)&dv,  g_d);
    cudaGetSymbolAddress((void**)&hh,  g_hh);  cudaGetSymbolAddress((void**)&hl,  g_hl);
    cudaGetSymbolAddress((void**)&h1h, g_h1h); cudaGetSymbolAddress((void**)&h1l, g_h1l);
    cudaGetSymbolAddress((void**)&h2,  g_h2);
    u16 *wb1h, *wb1l, *wb2h, *wb2l, *wt0h, *wt0l, *wt1h, *wt1l;
    cudaGetSymbolAddress((void**)&wb1h, g_Wb1h); cudaGetSymbolAddress((void**)&wb1l, g_Wb1l);
    cudaGetSymbolAddress((void**)&wb2h, g_Wb2h); cudaGetSymbolAddress((void**)&wb2l, g_Wb2l);
    cudaGetSymbolAddress((void**)&wt0h, g_Wt0h); cudaGetSymbolAddress((void**)&wt0l, g_Wt0l);
    cudaGetSymbolAddress((void**)&wt1h, g_Wt1h); cudaGetSymbolAddress((void**)&wt1l, g_Wt1l);

    // dynamic smem opt-in (idempotent, non-stream API: capture-safe)
    const int SM256 = 3 * (256 + 2 * 256) * 40 * 2;   // 184,320 B
    const int SM64  = 3 * (256 + 2 *  64) * 40 * 2;   //  92,160 B
    const int SMEI  = EROWS * 28 * 68 * 4;            //  60,928 B
    cudaFuncSetAttribute((const void*)gemm_mma<512, 256, 1>,
                         cudaFuncAttributeMaxDynamicSharedMemorySize, SM256);
    cudaFuncSetAttribute((const void*)gemm_mma<512, 256, 0>,
                         cudaFuncAttributeMaxDynamicSharedMemorySize, SM256);
    cudaFuncSetAttribute((const void*)gemm_mma<256, 64, 2>,
                         cudaFuncAttributeMaxDynamicSharedMemorySize, SM64);
    cudaFuncSetAttribute((const void*)embed_interact2,
                         cudaFuncAttributeMaxDynamicSharedMemorySize, SMEI);

    // 0) weight transpose + bf16 split (one launch)
    prep_all<<<248, 256>>>(Wb1, Wb2, Wt0, Wt1,
                           wb1h, wb1l, wb2h, wb2l, wt0h, wt0l, wt1h, wt1l);

    // 1) bottom L0: dense -> x0 (split)
    bot0_kernel<<<BATCH / 32, 256>>>(dense, Wb0, bb0, x0h, x0l);

    // 2) bottom L1: x0 -> x1 (split out)  N=256 K=512
    gemm_mma<512, 256, 1><<<dim3(1, BATCH / 128), 512, SM256>>>(
        x0h, x0l, 512, wb1h, wb1l, bb1, nullptr, 0, x1h, x1l, 256, 16);

    // 3) bottom L2: x1 -> d fp32 + hh/hl cols 0..63  N=64 K=256
    gemm_mma<256, 64, 2><<<dim3(1, BATCH / 128), 256, SM64>>>(
        x1h, x1l, 256, wb2h, wb2l, bb2, dv, 64, hh, hl, 448, 8);

    // 4) embedding gather + interaction -> hh/hl cols 64..414 (split direct)
    embed_interact2<<<BATCH / EROWS, 256, SMEI>>>(sidx, emb, dv, hh, hl);

    // 5) top L0: h -> h1 (split out)  N=512 K=448
    gemm_mma<512, 256, 1><<<dim3(2, BATCH / 128), 512, SM256>>>(
        hh, hl, 448, wt0h, wt0l, bt0, nullptr, 0, h1h, h1l, 512, 14);

    // 6) top L1: h1 -> h2 (fp32)  N=256 K=512
    gemm_mma<512, 256, 0><<<dim3(1, BATCH / 128), 512, SM256>>>(
        h1h, h1l, 512, wt1h, wt1l, bt1, h2, 256, nullptr, nullptr, 0, 16);

    // 7) final dot + sigmoid
    top_final_kernel<<<BATCH / 8, 256>>>(h2, Wt2, bt2, out);
}

// round 9
// speedup vs baseline: 1.6713x; 1.0500x over previous
#include <cuda_runtime.h>
#include <cuda_bf16.h>
#include <math.h>

#define BATCH   16384
#define NTAB    26
#define VOCABSZ 100000

typedef unsigned long long u64;
typedef unsigned int       u32;
typedef unsigned short     u16;

// ---------------- scratch (bss, zero-initialized, no allocation) --------
__device__ u16   g_x0h[BATCH * 512], g_x0l[BATCH * 512];   // bottom L0 out (split)
__device__ u16   g_x1h[BATCH * 256], g_x1l[BATCH * 256];   // bottom L1 out (split)
__device__ float g_d  [BATCH * 64];                        // bottom L2 out (fp32 d)
__device__ u16   g_hh [BATCH * 448], g_hl [BATCH * 448];   // split h (d|inter|zero pad)
__device__ u16   g_h1h[BATCH * 512], g_h1l[BATCH * 512];   // top L0 out (split)
// transposed + split bf16 weights  (Wt[n][k] = W[k][n]; k >= Kreal zeroed)
__device__ u16 g_Wb1h[256 * 512], g_Wb1l[256 * 512];
__device__ u16 g_Wb2h[ 64 * 256], g_Wb2l[ 64 * 256];
__device__ u16 g_Wt0h[512 * 448], g_Wt0l[512 * 448];
__device__ u16 g_Wt1h[256 * 512], g_Wt1l[256 * 512];

// ---------------- helpers ----------------
__device__ __forceinline__ u32 smem_u32(const void* p) {
    u32 a;
    asm("{ .reg .u64 t; cvta.to.shared.u64 t, %1; cvt.u32.u64 %0, t; }"
        : "=r"(a) : "l"(p));
    return a;
}

// split fp32 pair (a,b) into packed bf16 hi (a->lo half) and bf16 residuals
__device__ __forceinline__ void split2(float a, float b, u32& hi, u32& lo) {
    asm("cvt.rn.bf16x2.f32 %0, %1, %2;" : "=r"(hi) : "f"(b), "f"(a));
    float ra = a - __uint_as_float(hi << 16);
    float rb = b - __uint_as_float(hi & 0xFFFF0000u);
    asm("cvt.rn.bf16x2.f32 %0, %1, %2;" : "=r"(lo) : "f"(rb), "f"(ra));
}

__device__ __forceinline__ void ldmx4(u32* r, u32 addr) {
    asm volatile("ldmatrix.sync.aligned.m8n8.x4.shared.b16 {%0,%1,%2,%3}, [%4];"
                 : "=r"(r[0]), "=r"(r[1]), "=r"(r[2]), "=r"(r[3]) : "r"(addr));
}
__device__ __forceinline__ void mma16816(float* c, const u32* a, const u32* b) {
    asm volatile(
        "mma.sync.aligned.m16n8k16.row.col.f32.bf16.bf16.f32 "
        "{%0,%1,%2,%3}, {%4,%5,%6,%7}, {%8,%9}, {%0,%1,%2,%3};"
        : "+f"(c[0]), "+f"(c[1]), "+f"(c[2]), "+f"(c[3])
        : "r"(a[0]), "r"(a[1]), "r"(a[2]), "r"(a[3]), "r"(b[0]), "r"(b[1]));
}
__device__ __forceinline__ void cp16(u32 dst, const void* src) {
    asm volatile("cp.async.cg.shared.global [%0], [%1], 16;"
                 :: "r"(dst), "l"(__cvta_generic_to_global(src)));
}

// =====================================================================
// Weight prep (single launch): all 4 weights transposed + split.
// =====================================================================
__global__ void __launch_bounds__(256) prep_all(
    const float* __restrict__ Wb1, const float* __restrict__ Wb2,
    const float* __restrict__ Wt0, const float* __restrict__ Wt1,
    u16* __restrict__ b1h, u16* __restrict__ b1l,
    u16* __restrict__ b2h, u16* __restrict__ b2l,
    u16* __restrict__ t0h, u16* __restrict__ t0l,
    u16* __restrict__ t1h, u16* __restrict__ t1l)
{
    const int i = blockIdx.x * 256 + threadIdx.x;
    const float* W; u16 *H, *L; int N, Kreal, Kpad, li;
    if (i < 16384)      { W = Wb1; H = b1h; L = b1l; N = 256; Kreal = 512; Kpad = 512; li = i; }
    else if (i < 18432) { W = Wb2; H = b2h; L = b2l; N =  64; Kreal = 256; Kpad = 256; li = i - 16384; }
    else if (i < 47104) { W = Wt0; H = t0h; L = t0l; N = 512; Kreal = 415; Kpad = 448; li = i - 18432; }
    else if (i < 63488) { W = Wt1; H = t1h; L = t1l; N = 256; Kreal = 512; Kpad = 512; li = i - 47104; }
    else return;
    const int n  = li / (Kpad / 8);
    const int k8 = (li % (Kpad / 8)) * 8;
    u16 hb[8], lb[8];
#pragma unroll
    for (int j = 0; j < 8; j++) {
        const int k = k8 + j;
        const float w = (k < Kreal) ? W[(size_t)k * N + n] : 0.f;
        u32 h, l;
        split2(w, 0.f, h, l);
        hb[j] = (u16)(h & 0xFFFFu);
        lb[j] = (u16)(l & 0xFFFFu);
    }
    *(uint4*)(H + (size_t)n * Kpad + k8) = *(uint4*)hb;
    *(uint4*)(L + (size_t)n * Kpad + k8) = *(uint4*)lb;
}

// =====================================================================
// Warp-MMA split-bf16 GEMM: out = relu(A @ Wt^T + bias)
// 3-term: Ah*Bh + Ah*Bl + Al*Bh, fp32 accum. BM=128, BK=32,
// NSTAGE-deep cp.async pipeline, ldmatrix + mma.m16n8k16.
// OMODE: 0 = fp32 C;  1 = split bf16 Oh/Ol;  2 = both;
//        3 = fused final: out2[row] = sigmoid(dot(row, w2) + b2) (BN==256, grid.x==1)
// =====================================================================
template<int THREADS, int BN, int OMODE, int NSTAGE>
__global__ void __launch_bounds__(THREADS, (THREADS == 256 ? 2 : 1))
gemm_mma(
    const u16* __restrict__ Ah, const u16* __restrict__ Al, int Kpad,
    const u16* __restrict__ Bh, const u16* __restrict__ Bl,
    const float* __restrict__ bias,
    float* __restrict__ C, int ldc,
    u16* __restrict__ Oh, u16* __restrict__ Ol, int Kout,
    int NC,
    float* __restrict__ out2, const float* __restrict__ w2,
    const float* __restrict__ b2)
{
    constexpr int SR  = 40;                 // bf16 elems per smem row (80B)
    constexpr int WNC = THREADS / 128;      // n-warp groups
    constexpr int NW  = BN / WNC;           // cols per warp
    constexpr int NFR = NW / 8;             // n8 frags per warp
    constexpr int SSZ = (256 + 2 * BN) * SR;// bf16 elems per stage
    extern __shared__ u16 sm[];
    const u32 sbase = smem_u32(sm);
    const int tid = threadIdx.x, wid = tid >> 5, lane = tid & 31;
    const int wm = wid & 3, wn = wid >> 2;
    const int bm = blockIdx.y * 128, bn = blockIdx.x * BN;

    float acc[2][NFR][4];
#pragma unroll
    for (int m = 0; m < 2; m++)
#pragma unroll
        for (int n = 0; n < NFR; n++)
#pragma unroll
            for (int j = 0; j < 4; j++) acc[m][n][j] = 0.f;

    auto prefetch = [&](int c, int buf) {
        const u32 sb = sbase + (u32)buf * SSZ * 2;
        constexpr int AOPS = 1024 / THREADS;
#pragma unroll
        for (int i = 0; i < AOPS; i++) {
            const int g = tid + i * THREADS;
            const int arr = g >> 9, r = (g >> 2) & 127, ch = g & 3;
            const u16* src = (arr ? Al : Ah) + (size_t)(bm + r) * Kpad + c * 32 + ch * 8;
            cp16(sb + (u32)(arr * 128 * SR + r * SR + ch * 8) * 2, src);
        }
        constexpr int BOPS = BN * 8 / THREADS;
#pragma unroll
        for (int i = 0; i < BOPS; i++) {
            const int g = tid + i * THREADS;
            const int arr = g / (BN * 4), r = (g >> 2) & (BN - 1), ch = g & 3;
            const u16* src = (arr ? Bl : Bh) + (size_t)(bn + r) * Kpad + c * 32 + ch * 8;
            cp16(sb + (u32)((256 + arr * BN) * SR + r * SR + ch * 8) * 2, src);
        }
    };

    prefetch(0, 0);
    asm volatile("cp.async.commit_group;" ::: "memory");
    if (NSTAGE == 3) {
        prefetch(1, 1);
        asm volatile("cp.async.commit_group;" ::: "memory");
    }

    for (int c = 0; c < NC; c++) {
        asm volatile("cp.async.wait_group %0;" :: "n"(NSTAGE - 2) : "memory");
        __syncthreads();
        if (c + NSTAGE - 1 < NC) prefetch(c + NSTAGE - 1, (c + NSTAGE - 1) % NSTAGE);
        asm volatile("cp.async.commit_group;" ::: "memory");

        const u32 sA  = sbase + (u32)(c % NSTAGE) * SSZ * 2;
        const u32 sBs = sA + 256 * SR * 2;
#pragma unroll
        for (int ks = 0; ks < 2; ks++) {
            u32 ah[2][4], al_[2][4];
#pragma unroll
            for (int mf = 0; mf < 2; mf++) {
                const u32 ra = sA + (u32)(((wm * 32 + mf * 16 + (lane & 15)) * SR
                                           + ks * 16 + (lane >> 4) * 8) * 2);
                ldmx4(ah[mf], ra);
                ldmx4(al_[mf], ra + 128 * SR * 2);
            }
#pragma unroll
            for (int nf2 = 0; nf2 < NFR / 2; nf2++) {
                const u32 rb = sBs + (u32)(((wn * NW + nf2 * 16 + (lane & 7)
                                             + ((lane >> 4) << 3)) * SR
                                            + ks * 16 + ((lane >> 3) & 1) * 8) * 2);
                u32 bh4[4], bl4[4];
                ldmx4(bh4, rb);
                ldmx4(bl4, rb + BN * SR * 2);
#pragma unroll
                for (int hf = 0; hf < 2; hf++) {
                    const int nf = nf2 * 2 + hf;
                    const u32* bh2 = bh4 + hf * 2;
                    const u32* bl2 = bl4 + hf * 2;
#pragma unroll
                    for (int mf = 0; mf < 2; mf++) {
                        mma16816(acc[mf][nf], ah[mf],  bh2);
                        mma16816(acc[mf][nf], ah[mf],  bl2);
                        mma16816(acc[mf][nf], al_[mf], bh2);
                    }
                }
            }
        }
    }

    // ---------------- epilogue ----------------
    if (OMODE == 3) {
        // fused final layer: dot with w2, reduce, sigmoid.
        asm volatile("cp.async.wait_group 0;" ::: "memory");
        __syncthreads();
        float* srow = (float*)sm;
        if (tid < 128) srow[tid] = 0.f;
        __syncthreads();
        float p[4] = {0.f, 0.f, 0.f, 0.f};
#pragma unroll
        for (int mf = 0; mf < 2; mf++) {
#pragma unroll
            for (int nf = 0; nf < NFR; nf++) {
                const int cc = bn + wn * NW + nf * 8 + 2 * (lane & 3);
                const float b0 = bias[cc], b1 = bias[cc + 1];
                const float w0 = w2[cc], w1 = w2[cc + 1];
                const float v0 = fmaxf(acc[mf][nf][0] + b0, 0.f);
                const float v1 = fmaxf(acc[mf][nf][1] + b1, 0.f);
                const float v2 = fmaxf(acc[mf][nf][2] + b0, 0.f);
                const float v3 = fmaxf(acc[mf][nf][3] + b1, 0.f);
                p[mf * 2 + 0] += v0 * w0 + v1 * w1;
                p[mf * 2 + 1] += v2 * w0 + v3 * w1;
            }
        }
#pragma unroll
        for (int s = 1; s <= 2; s <<= 1)
#pragma unroll
            for (int j = 0; j < 4; j++)
                p[j] += __shfl_xor_sync(0xffffffffu, p[j], s);
        if ((lane & 3) == 0) {
            const int r0 = wm * 32 + (lane >> 2);
            atomicAdd(&srow[r0],      p[0]);
            atomicAdd(&srow[r0 + 8],  p[1]);
            atomicAdd(&srow[r0 + 16], p[2]);
            atomicAdd(&srow[r0 + 24], p[3]);
        }
        __syncthreads();
        if (tid < 128)
            out2[bm + tid] = 1.f / (1.f + expf(-(srow[tid] + b2[0])));
    } else {
#pragma unroll
        for (int mf = 0; mf < 2; mf++) {
#pragma unroll
            for (int nf = 0; nf < NFR; nf++) {
                const int row0 = bm + wm * 32 + mf * 16 + (lane >> 2);
                const int cc   = bn + wn * NW + nf * 8 + 2 * (lane & 3);
                const float b0 = bias[cc], b1 = bias[cc + 1];
                const float v0 = fmaxf(acc[mf][nf][0] + b0, 0.f);
                const float v1 = fmaxf(acc[mf][nf][1] + b1, 0.f);
                const float v2 = fmaxf(acc[mf][nf][2] + b0, 0.f);
                const float v3 = fmaxf(acc[mf][nf][3] + b1, 0.f);
                if (OMODE != 1) {
                    *(float2*)(C + (size_t)row0 * ldc + cc)       = make_float2(v0, v1);
                    *(float2*)(C + (size_t)(row0 + 8) * ldc + cc) = make_float2(v2, v3);
                }
                if (OMODE != 0) {
                    u32 h, l;
                    split2(v0, v1, h, l);
                    *(u32*)(Oh + (size_t)row0 * Kout + cc) = h;
                    *(u32*)(Ol + (size_t)row0 * Kout + cc) = l;
                    split2(v2, v3, h, l);
                    *(u32*)(Oh + (size_t)(row0 + 8) * Kout + cc) = h;
                    *(u32*)(Ol + (size_t)(row0 + 8) * Kout + cc) = l;
                }
            }
        }
    }
}

// =====================================================================
// Bottom MLP layer 0: x0 = relu(dense[16384,13] @ Wb0 + bb0), split-bf16 out
// =====================================================================
__global__ void __launch_bounds__(256) bot0_kernel(
    const float* __restrict__ dense, const float* __restrict__ W,
    const float* __restrict__ bias, u16* __restrict__ xh, u16* __restrict__ xl)
{
    __shared__ float sW[13 * 512];
    __shared__ float sB[512];
    __shared__ float sD[32 * 13];
    const int tid = threadIdx.x;
    const int rbase = blockIdx.x * 32;

    for (int i = tid; i < 13 * 512; i += 256) sW[i] = W[i];
    for (int i = tid; i < 512;      i += 256) sB[i] = bias[i];
    for (int i = tid; i < 32 * 13;  i += 256) sD[i] = dense[(size_t)rbase * 13 + i];
    __syncthreads();

    const int q  = tid & 127;
    const int rs = tid >> 7;
    const int c0 = q * 4;

    float4 w[13];
#pragma unroll
    for (int k = 0; k < 13; k++) w[k] = *(const float4*)&sW[k * 512 + c0];
    const float4 bq = *(const float4*)&sB[c0];

    for (int rr = 0; rr < 16; rr++) {
        const int r = rs * 16 + rr;
        float4 acc = bq;
#pragma unroll
        for (int k = 0; k < 13; k++) {
            const float a = sD[r * 13 + k];
            acc.x += a * w[k].x; acc.y += a * w[k].y;
            acc.z += a * w[k].z; acc.w += a * w[k].w;
        }
        acc.x = fmaxf(acc.x, 0.f); acc.y = fmaxf(acc.y, 0.f);
        acc.z = fmaxf(acc.z, 0.f); acc.w = fmaxf(acc.w, 0.f);
        u32 h0, l0, h1, l1;
        split2(acc.x, acc.y, h0, l0);
        split2(acc.z, acc.w, h1, l1);
        const size_t o = (size_t)(rbase + r) * 512 + c0;
        *(uint2*)(xh + o) = make_uint2(h0, h1);
        *(uint2*)(xl + o) = make_uint2(l0, l1);
    }
}

// =====================================================================
// Embedding gather + pairwise interaction, 4x4 vector tiles,
// split-bf16 output written directly into hh/hl (cols 64..414).
// =====================================================================
#define EROWS 8

__global__ void __launch_bounds__(256) embed_interact2(
    const u64* __restrict__ sidx, const float* __restrict__ emb,
    const float* __restrict__ dvec,
    u16* __restrict__ hh, u16* __restrict__ hl)
{
    extern __shared__ float Tsh[];
    __shared__ int s_is32;
    float4* T4 = (float4*)Tsh;
    const u32 sbase = smem_u32(Tsh);
    const int tid = threadIdx.x;
    const int rbase = blockIdx.x * EROWS;

    if (tid == 0) {
        int f = 0;
#pragma unroll
        for (int i = 0; i < 16; i++)
            if (sidx[i] >> 32) f = 1;
        s_is32 = f;
    }
    __syncthreads();
    const bool is32 = (s_is32 != 0);
    const int* sidx32 = (const int*)sidx;

    for (int u = tid; u < EROWS * 26 * 16; u += 256) {
        const int v = u >> 4, f = u & 15;
        const int r = v / 26, t = v - r * 26;
        const int grow = rbase + r;
        long long idx;
        if (is32) idx = (long long)sidx32[grow * 26 + t];
        else      idx = (long long)sidx[grow * 26 + t];
        const float* src = emb + ((size_t)t * VOCABSZ + (size_t)idx) * 64 + f * 4;
        cp16(sbase + (u32)(((r * 28 + t) * 17 + f) * 16), src);
    }
    for (int u = tid; u < EROWS * 16; u += 256) {
        const int r = u >> 4, f = u & 15;
        cp16(sbase + (u32)(((r * 28 + 26) * 17 + f) * 16),
             dvec + (size_t)(rbase + r) * 64 + f * 4);
        T4[(r * 28 + 27) * 17 + f] = make_float4(0.f, 0.f, 0.f, 0.f);
    }
    asm volatile("cp.async.commit_group;" ::: "memory");
    asm volatile("cp.async.wait_group 0;" ::: "memory");
    __syncthreads();

    const int task = tid;
    if (task < EROWS * 28) {
        const int r = task / 28, tt = task - r * 28;
        const int grow = rbase + r;
        u16* hrh = hh + (size_t)grow * 448 + 64;
        u16* hrl = hl + (size_t)grow * 448 + 64;
        const float4* bb = T4 + (size_t)r * 28 * 17;

        if (tt < 21) {
            int ti = 1;
            while ((ti * (ti + 1)) / 2 <= tt) ti++;
            const int tj = tt - ti * (ti - 1) / 2;
            const float4* Ti = bb + (4 * ti) * 17;
            const float4* Tj = bb + (4 * tj) * 17;
            float a[4][4];
#pragma unroll
            for (int ii = 0; ii < 4; ii++)
#pragma unroll
                for (int jj = 0; jj < 4; jj++) a[ii][jj] = 0.f;
#pragma unroll
            for (int f = 0; f < 16; f++) {
                float4 x[4], y[4];
#pragma unroll
                for (int ii = 0; ii < 4; ii++) x[ii] = Ti[ii * 17 + f];
#pragma unroll
                for (int jj = 0; jj < 4; jj++) y[jj] = Tj[jj * 17 + f];
#pragma unroll
                for (int ii = 0; ii < 4; ii++)
#pragma unroll
                    for (int jj = 0; jj < 4; jj++)
                        a[ii][jj] += x[ii].x * y[jj].x + x[ii].y * y[jj].y
                                   + x[ii].z * y[jj].z + x[ii].w * y[jj].w;
            }
#pragma unroll
            for (int ii = 0; ii < 4; ii++) {
                const int i = 4 * ti + ii;
                if (i < 27) {
                    const int base_i = i * (i - 1) / 2;
#pragma unroll
                    for (int jj = 0; jj < 4; jj++) {
                        const int j = 4 * tj + jj;
                        u32 h, l;
                        split2(a[ii][jj], 0.f, h, l);
                        hrh[base_i + j] = (u16)h;
                        hrl[base_i + j] = (u16)l;
                    }
                }
            }
        } else {
            const int ti = tt - 21;
            const float4* Ti = bb + (4 * ti) * 17;
            float a[6];
#pragma unroll
            for (int p = 0; p < 6; p++) a[p] = 0.f;
#pragma unroll
            for (int f = 0; f < 16; f++) {
                float4 x[4];
#pragma unroll
                for (int ii = 0; ii < 4; ii++) x[ii] = Ti[ii * 17 + f];
                a[0] += x[1].x * x[0].x + x[1].y * x[0].y + x[1].z * x[0].z + x[1].w * x[0].w;
                a[1] += x[2].x * x[0].x + x[2].y * x[0].y + x[2].z * x[0].z + x[2].w * x[0].w;
                a[2] += x[2].x * x[1].x + x[2].y * x[1].y + x[2].z * x[1].z + x[2].w * x[1].w;
                a[3] += x[3].x * x[0].x + x[3].y * x[0].y + x[3].z * x[0].z + x[3].w * x[0].w;
                a[4] += x[3].x * x[1].x + x[3].y * x[1].y + x[3].z * x[1].z + x[3].w * x[1].w;
                a[5] += x[3].x * x[2].x + x[3].y * x[2].y + x[3].z * x[2].z + x[3].w * x[2].w;
            }
            const int pi[6] = {1, 2, 2, 3, 3, 3};
            const int pj[6] = {0, 0, 1, 0, 1, 2};
#pragma unroll
            for (int p = 0; p < 6; p++) {
                const int i = 4 * ti + pi[p], j = 4 * ti + pj[p];
                if (i < 27) {
                    u32 h, l;
                    split2(a[p], 0.f, h, l);
                    hrh[i * (i - 1) / 2 + j] = (u16)h;
                    hrl[i * (i - 1) / 2 + j] = (u16)l;
                }
            }
        }
    }
}

// =====================================================================
// launch
// =====================================================================
extern "C" void kernel_launch(void* const* d_in, const int* in_sizes, int n_in,
                              void* d_out, int out_size)
{
    const float* dense = (const float*)d_in[0];
    const u64*   sidx  = (const u64*)  d_in[1];
    const float* emb   = (const float*)d_in[2];
    const float* Wb0 = (const float*)d_in[3];  const float* bb0 = (const float*)d_in[4];
    const float* Wb1 = (const float*)d_in[5];  const float* bb1 = (const float*)d_in[6];
    const float* Wb2 = (const float*)d_in[7];  const float* bb2 = (const float*)d_in[8];
    const float* Wt0 = (const float*)d_in[9];  const float* bt0 = (const float*)d_in[10];
    const float* Wt1 = (const float*)d_in[11]; const float* bt1 = (const float*)d_in[12];
    const float* Wt2 = (const float*)d_in[13]; const float* bt2 = (const float*)d_in[14];
    float* out = (float*)d_out;

    u16 *x0h, *x0l, *x1h, *x1l, *hh, *hl, *h1h, *h1l;
    float *dv;
    cudaGetSymbolAddress((void**)&x0h, g_x0h); cudaGetSymbolAddress((void**)&x0l, g_x0l);
    cudaGetSymbolAddress((void**)&x1h, g_x1h); cudaGetSymbolAddress((void**)&x1l, g_x1l);
    cudaGetSymbolAddress((void**)&dv,  g_d);
    cudaGetSymbolAddress((void**)&hh,  g_hh);  cudaGetSymbolAddress((void**)&hl,  g_hl);
    cudaGetSymbolAddress((void**)&h1h, g_h1h); cudaGetSymbolAddress((void**)&h1l, g_h1l);
    u16 *wb1h, *wb1l, *wb2h, *wb2l, *wt0h, *wt0l, *wt1h, *wt1l;
    cudaGetSymbolAddress((void**)&wb1h, g_Wb1h); cudaGetSymbolAddress((void**)&wb1l, g_Wb1l);
    cudaGetSymbolAddress((void**)&wb2h, g_Wb2h); cudaGetSymbolAddress((void**)&wb2l, g_Wb2l);
    cudaGetSymbolAddress((void**)&wt0h, g_Wt0h); cudaGetSymbolAddress((void**)&wt0l, g_Wt0l);
    cudaGetSymbolAddress((void**)&wt1h, g_Wt1h); cudaGetSymbolAddress((void**)&wt1l, g_Wt1l);

    // dynamic smem opt-in (idempotent, non-stream API: capture-safe)
    const int SM256 = 3 * (256 + 2 * 256) * 40 * 2;   // 184,320 B (BN=256, 3-stage)
    const int SM128 = 2 * (256 + 2 * 128) * 40 * 2;   //  81,920 B (BN=128, 2-stage)
    const int SM64  = 3 * (256 + 2 *  64) * 40 * 2;   //  92,160 B (BN=64, 3-stage)
    const int SMEI  = EROWS * 28 * 68 * 4;            //  60,928 B
    cudaFuncSetAttribute((const void*)gemm_mma<256, 128, 1, 2>,
                         cudaFuncAttributeMaxDynamicSharedMemorySize, SM128);
    cudaFuncSetAttribute((const void*)gemm_mma<512, 64, 2, 3>,
                         cudaFuncAttributeMaxDynamicSharedMemorySize, SM64);
    cudaFuncSetAttribute((const void*)gemm_mma<512, 256, 1, 3>,
                         cudaFuncAttributeMaxDynamicSharedMemorySize, SM256);
    cudaFuncSetAttribute((const void*)gemm_mma<512, 256, 3, 3>,
                         cudaFuncAttributeMaxDynamicSharedMemorySize, SM256);
    cudaFuncSetAttribute((const void*)embed_interact2,
                         cudaFuncAttributeMaxDynamicSharedMemorySize, SMEI);

    // 0) weight transpose + bf16 split
    prep_all<<<248, 256>>>(Wb1, Wb2, Wt0, Wt1,
                           wb1h, wb1l, wb2h, wb2l, wt0h, wt0l, wt1h, wt1l);

    // 1) bottom L0: dense -> x0 (split)
    bot0_kernel<<<BATCH / 32, 256>>>(dense, Wb0, bb0, x0h, x0l);

    // 2) bottom L1: x0 -> x1 (split out)  N=256 K=512  [BN=128, 2 CTA/SM test]
    gemm_mma<256, 128, 1, 2><<<dim3(2, BATCH / 128), 256, SM128>>>(
        x0h, x0l, 512, wb1h, wb1l, bb1, nullptr, 0, x1h, x1l, 256, 16,
        nullptr, nullptr, nullptr);

    // 3) bottom L2: x1 -> d fp32 + hh/hl cols 0..63  N=64 K=256  [512 thr]
    gemm_mma<512, 64, 2, 3><<<dim3(1, BATCH / 128), 512, SM64>>>(
        x1h, x1l, 256, wb2h, wb2l, bb2, dv, 64, hh, hl, 448, 8,
        nullptr, nullptr, nullptr);

    // 4) embedding gather + interaction -> hh/hl cols 64..414
    embed_interact2<<<BATCH / EROWS, 256, SMEI>>>(sidx, emb, dv, hh, hl);

    // 5) top L0: h -> h1 (split out)  N=512 K=448
    gemm_mma<512, 256, 1, 3><<<dim3(2, BATCH / 128), 512, SM256>>>(
        hh, hl, 448, wt0h, wt0l, bt0, nullptr, 0, h1h, h1l, 512, 14,
        nullptr, nullptr, nullptr);

    // 6) top L1 + final fused: h1 -> sigmoid(h2 . Wt2 + bt2) -> out
    gemm_mma<512, 256, 3, 3><<<dim3(1, BATCH / 128), 512, SM256>>>(
        h1h, h1l, 512, wt1h, wt1l, bt1, nullptr, 0, nullptr, nullptr, 0, 16,
        out, Wt2, bt2);
}

// round 11
// speedup vs baseline: 1.7593x; 1.0527x over previous
#include <cuda_runtime.h>
#include <cuda_bf16.h>
#include <math.h>

#define BATCH   16384
#define NTAB    26
#define VOCABSZ 100000

typedef unsigned long long u64;
typedef unsigned int       u32;
typedef unsigned short     u16;

// ---------------- scratch (bss, zero-initialized, no allocation) --------
__device__ u16   g_x0h[BATCH * 512], g_x0l[BATCH * 512];   // bottom L0 out (split)
__device__ u16   g_x1h[BATCH * 256], g_x1l[BATCH * 256];   // bottom L1 out (split)
__device__ float g_d  [BATCH * 64];                        // bottom L2 out (fp32 d)
__device__ u16   g_hh [BATCH * 448], g_hl [BATCH * 448];   // split h (d|inter|zero pad)
__device__ u16   g_h1h[BATCH * 512], g_h1l[BATCH * 512];   // top L0 out (split)
// transposed + split bf16 weights  (Wt[n][k] = W[k][n]; k >= Kreal zeroed)
__device__ u16 g_Wb1h[256 * 512], g_Wb1l[256 * 512];
__device__ u16 g_Wb2h[ 64 * 256], g_Wb2l[ 64 * 256];
__device__ u16 g_Wt0h[512 * 448], g_Wt0l[512 * 448];
__device__ u16 g_Wt1h[256 * 512], g_Wt1l[256 * 512];

// ---------------- helpers ----------------
__device__ __forceinline__ u32 smem_u32(const void* p) {
    u32 a;
    asm("{ .reg .u64 t; cvta.to.shared.u64 t, %1; cvt.u32.u64 %0, t; }"
        : "=r"(a) : "l"(p));
    return a;
}

// split fp32 pair (a,b) into packed bf16 hi (a->lo half) and bf16 residuals
__device__ __forceinline__ void split2(float a, float b, u32& hi, u32& lo) {
    asm("cvt.rn.bf16x2.f32 %0, %1, %2;" : "=r"(hi) : "f"(b), "f"(a));
    float ra = a - __uint_as_float(hi << 16);
    float rb = b - __uint_as_float(hi & 0xFFFF0000u);
    asm("cvt.rn.bf16x2.f32 %0, %1, %2;" : "=r"(lo) : "f"(rb), "f"(ra));
}

__device__ __forceinline__ void ldmx4(u32* r, u32 addr) {
    asm volatile("ldmatrix.sync.aligned.m8n8.x4.shared.b16 {%0,%1,%2,%3}, [%4];"
                 : "=r"(r[0]), "=r"(r[1]), "=r"(r[2]), "=r"(r[3]) : "r"(addr));
}
__device__ __forceinline__ void mma16816(float* c, const u32* a, const u32* b) {
    asm volatile(
        "mma.sync.aligned.m16n8k16.row.col.f32.bf16.bf16.f32 "
        "{%0,%1,%2,%3}, {%4,%5,%6,%7}, {%8,%9}, {%0,%1,%2,%3};"
        : "+f"(c[0]), "+f"(c[1]), "+f"(c[2]), "+f"(c[3])
        : "r"(a[0]), "r"(a[1]), "r"(a[2]), "r"(a[3]), "r"(b[0]), "r"(b[1]));
}
__device__ __forceinline__ void cp16(u32 dst, const void* src) {
    asm volatile("cp.async.cg.shared.global [%0], [%1], 16;"
                 :: "r"(dst), "l"(__cvta_generic_to_global(src)));
}
// 256-byte bulk async copy, completion via mbarrier complete_tx
__device__ __forceinline__ void cpbulk256(u32 dst, const void* src, u32 mbar) {
    asm volatile(
        "cp.async.bulk.shared::cta.global.mbarrier::complete_tx::bytes "
        "[%0], [%1], 256, [%2];"
        :: "r"(dst), "l"(__cvta_generic_to_global(src)), "r"(mbar) : "memory");
}

// =====================================================================
// Weight prep (single launch): all 4 weights transposed + split.
// =====================================================================
__global__ void __launch_bounds__(256) prep_all(
    const float* __restrict__ Wb1, const float* __restrict__ Wb2,
    const float* __restrict__ Wt0, const float* __restrict__ Wt1,
    u16* __restrict__ b1h, u16* __restrict__ b1l,
    u16* __restrict__ b2h, u16* __restrict__ b2l,
    u16* __restrict__ t0h, u16* __restrict__ t0l,
    u16* __restrict__ t1h, u16* __restrict__ t1l)
{
    const int i = blockIdx.x * 256 + threadIdx.x;
    const float* W; u16 *H, *L; int N, Kreal, Kpad, li;
    if (i < 16384)      { W = Wb1; H = b1h; L = b1l; N = 256; Kreal = 512; Kpad = 512; li = i; }
    else if (i < 18432) { W = Wb2; H = b2h; L = b2l; N =  64; Kreal = 256; Kpad = 256; li = i - 16384; }
    else if (i < 47104) { W = Wt0; H = t0h; L = t0l; N = 512; Kreal = 415; Kpad = 448; li = i - 18432; }
    else if (i < 63488) { W = Wt1; H = t1h; L = t1l; N = 256; Kreal = 512; Kpad = 512; li = i - 47104; }
    else return;
    const int n  = li / (Kpad / 8);
    const int k8 = (li % (Kpad / 8)) * 8;
    u16 hb[8], lb[8];
#pragma unroll
    for (int j = 0; j < 8; j++) {
        const int k = k8 + j;
        const float w = (k < Kreal) ? W[(size_t)k * N + n] : 0.f;
        u32 h, l;
        split2(w, 0.f, h, l);
        hb[j] = (u16)(h & 0xFFFFu);
        lb[j] = (u16)(l & 0xFFFFu);
    }
    *(uint4*)(H + (size_t)n * Kpad + k8) = *(uint4*)hb;
    *(uint4*)(L + (size_t)n * Kpad + k8) = *(uint4*)lb;
}

// =====================================================================
// Warp-MMA split-bf16 GEMM (unchanged from R9-passing build).
// OMODE: 0 = fp32 C; 1 = split bf16; 2 = both; 3 = fused final sigmoid.
// =====================================================================
template<int THREADS, int BN, int OMODE, int NSTAGE>
__global__ void __launch_bounds__(THREADS, (THREADS == 256 ? 2 : 1))
gemm_mma(
    const u16* __restrict__ Ah, const u16* __restrict__ Al, int Kpad,
    const u16* __restrict__ Bh, const u16* __restrict__ Bl,
    const float* __restrict__ bias,
    float* __restrict__ C, int ldc,
    u16* __restrict__ Oh, u16* __restrict__ Ol, int Kout,
    int NC,
    float* __restrict__ out2, const float* __restrict__ w2,
    const float* __restrict__ b2)
{
    constexpr int SR  = 40;
    constexpr int WNC = THREADS / 128;
    constexpr int NW  = BN / WNC;
    constexpr int NFR = NW / 8;
    constexpr int SSZ = (256 + 2 * BN) * SR;
    extern __shared__ u16 sm[];
    const u32 sbase = smem_u32(sm);
    const int tid = threadIdx.x, wid = tid >> 5, lane = tid & 31;
    const int wm = wid & 3, wn = wid >> 2;
    const int bm = blockIdx.y * 128, bn = blockIdx.x * BN;

    float acc[2][NFR][4];
#pragma unroll
    for (int m = 0; m < 2; m++)
#pragma unroll
        for (int n = 0; n < NFR; n++)
#pragma unroll
            for (int j = 0; j < 4; j++) acc[m][n][j] = 0.f;

    auto prefetch = [&](int c, int buf) {
        const u32 sb = sbase + (u32)buf * SSZ * 2;
        constexpr int AOPS = 1024 / THREADS;
#pragma unroll
        for (int i = 0; i < AOPS; i++) {
            const int g = tid + i * THREADS;
            const int arr = g >> 9, r = (g >> 2) & 127, ch = g & 3;
            const u16* src = (arr ? Al : Ah) + (size_t)(bm + r) * Kpad + c * 32 + ch * 8;
            cp16(sb + (u32)(arr * 128 * SR + r * SR + ch * 8) * 2, src);
        }
        constexpr int BOPS = BN * 8 / THREADS;
#pragma unroll
        for (int i = 0; i < BOPS; i++) {
            const int g = tid + i * THREADS;
            const int arr = g / (BN * 4), r = (g >> 2) & (BN - 1), ch = g & 3;
            const u16* src = (arr ? Bl : Bh) + (size_t)(bn + r) * Kpad + c * 32 + ch * 8;
            cp16(sb + (u32)((256 + arr * BN) * SR + r * SR + ch * 8) * 2, src);
        }
    };

    prefetch(0, 0);
    asm volatile("cp.async.commit_group;" ::: "memory");
    if (NSTAGE == 3) {
        prefetch(1, 1);
        asm volatile("cp.async.commit_group;" ::: "memory");
    }

    for (int c = 0; c < NC; c++) {
        asm volatile("cp.async.wait_group %0;" :: "n"(NSTAGE - 2) : "memory");
        __syncthreads();
        if (c + NSTAGE - 1 < NC) prefetch(c + NSTAGE - 1, (c + NSTAGE - 1) % NSTAGE);
        asm volatile("cp.async.commit_group;" ::: "memory");

        const u32 sA  = sbase + (u32)(c % NSTAGE) * SSZ * 2;
        const u32 sBs = sA + 256 * SR * 2;
#pragma unroll
        for (int ks = 0; ks < 2; ks++) {
            u32 ah[2][4], al_[2][4];
#pragma unroll
            for (int mf = 0; mf < 2; mf++) {
                const u32 ra = sA + (u32)(((wm * 32 + mf * 16 + (lane & 15)) * SR
                                           + ks * 16 + (lane >> 4) * 8) * 2);
                ldmx4(ah[mf], ra);
                ldmx4(al_[mf], ra + 128 * SR * 2);
            }
#pragma unroll
            for (int nf2 = 0; nf2 < NFR / 2; nf2++) {
                const u32 rb = sBs + (u32)(((wn * NW + nf2 * 16 + (lane & 7)
                                             + ((lane >> 4) << 3)) * SR
                                            + ks * 16 + ((lane >> 3) & 1) * 8) * 2);
                u32 bh4[4], bl4[4];
                ldmx4(bh4, rb);
                ldmx4(bl4, rb + BN * SR * 2);
#pragma unroll
                for (int hf = 0; hf < 2; hf++) {
                    const int nf = nf2 * 2 + hf;
                    const u32* bh2 = bh4 + hf * 2;
                    const u32* bl2 = bl4 + hf * 2;
#pragma unroll
                    for (int mf = 0; mf < 2; mf++) {
                        mma16816(acc[mf][nf], ah[mf],  bh2);
                        mma16816(acc[mf][nf], ah[mf],  bl2);
                        mma16816(acc[mf][nf], al_[mf], bh2);
                    }
                }
            }
        }
    }

    if (OMODE == 3) {
        asm volatile("cp.async.wait_group 0;" ::: "memory");
        __syncthreads();
        float* srow = (float*)sm;
        if (tid < 128) srow[tid] = 0.f;
        __syncthreads();
        float p[4] = {0.f, 0.f, 0.f, 0.f};
#pragma unroll
        for (int mf = 0; mf < 2; mf++) {
#pragma unroll
            for (int nf = 0; nf < NFR; nf++) {
                const int cc = bn + wn * NW + nf * 8 + 2 * (lane & 3);
                const float b0 = bias[cc], b1 = bias[cc + 1];
                const float w0 = w2[cc], w1 = w2[cc + 1];
                const float v0 = fmaxf(acc[mf][nf][0] + b0, 0.f);
                const float v1 = fmaxf(acc[mf][nf][1] + b1, 0.f);
                const float v2 = fmaxf(acc[mf][nf][2] + b0, 0.f);
                const float v3 = fmaxf(acc[mf][nf][3] + b1, 0.f);
                p[mf * 2 + 0] += v0 * w0 + v1 * w1;
                p[mf * 2 + 1] += v2 * w0 + v3 * w1;
            }
        }
#pragma unroll
        for (int s = 1; s <= 2; s <<= 1)
#pragma unroll
            for (int j = 0; j < 4; j++)
                p[j] += __shfl_xor_sync(0xffffffffu, p[j], s);
        if ((lane & 3) == 0) {
            const int r0 = wm * 32 + (lane >> 2);
            atomicAdd(&srow[r0],      p[0]);
            atomicAdd(&srow[r0 + 8],  p[1]);
            atomicAdd(&srow[r0 + 16], p[2]);
            atomicAdd(&srow[r0 + 24], p[3]);
        }
        __syncthreads();
        if (tid < 128)
            out2[bm + tid] = 1.f / (1.f + expf(-(srow[tid] + b2[0])));
    } else {
#pragma unroll
        for (int mf = 0; mf < 2; mf++) {
#pragma unroll
            for (int nf = 0; nf < NFR; nf++) {
                const int row0 = bm + wm * 32 + mf * 16 + (lane >> 2);
                const int cc   = bn + wn * NW + nf * 8 + 2 * (lane & 3);
                const float b0 = bias[cc], b1 = bias[cc + 1];
                const float v0 = fmaxf(acc[mf][nf][0] + b0, 0.f);
                const float v1 = fmaxf(acc[mf][nf][1] + b1, 0.f);
                const float v2 = fmaxf(acc[mf][nf][2] + b0, 0.f);
                const float v3 = fmaxf(acc[mf][nf][3] + b1, 0.f);
                if (OMODE != 1) {
                    *(float2*)(C + (size_t)row0 * ldc + cc)       = make_float2(v0, v1);
                    *(float2*)(C + (size_t)(row0 + 8) * ldc + cc) = make_float2(v2, v3);
                }
                if (OMODE != 0) {
                    u32 h, l;
                    split2(v0, v1, h, l);
                    *(u32*)(Oh + (size_t)row0 * Kout + cc) = h;
                    *(u32*)(Ol + (size_t)row0 * Kout + cc) = l;
                    split2(v2, v3, h, l);
                    *(u32*)(Oh + (size_t)(row0 + 8) * Kout + cc) = h;
                    *(u32*)(Ol + (size_t)(row0 + 8) * Kout + cc) = l;
                }
            }
        }
    }
}

// =====================================================================
// Bottom MLP layer 0: x0 = relu(dense[16384,13] @ Wb0 + bb0), split-bf16 out
// =====================================================================
__global__ void __launch_bounds__(256) bot0_kernel(
    const float* __restrict__ dense, const float* __restrict__ W,
    const float* __restrict__ bias, u16* __restrict__ xh, u16* __restrict__ xl)
{
    __shared__ float sW[13 * 512];
    __shared__ float sB[512];
    __shared__ float sD[32 * 13];
    const int tid = threadIdx.x;
    const int rbase = blockIdx.x * 32;

    for (int i = tid; i < 13 * 512; i += 256) sW[i] = W[i];
    for (int i = tid; i < 512;      i += 256) sB[i] = bias[i];
    for (int i = tid; i < 32 * 13;  i += 256) sD[i] = dense[(size_t)rbase * 13 + i];
    __syncthreads();

    const int q  = tid & 127;
    const int rs = tid >> 7;
    const int c0 = q * 4;

    float4 w[13];
#pragma unroll
    for (int k = 0; k < 13; k++) w[k] = *(const float4*)&sW[k * 512 + c0];
    const float4 bq = *(const float4*)&sB[c0];

    for (int rr = 0; rr < 16; rr++) {
        const int r = rs * 16 + rr;
        float4 acc = bq;
#pragma unroll
        for (int k = 0; k < 13; k++) {
            const float a = sD[r * 13 + k];
            acc.x += a * w[k].x; acc.y += a * w[k].y;
            acc.z += a * w[k].z; acc.w += a * w[k].w;
        }
        acc.x = fmaxf(acc.x, 0.f); acc.y = fmaxf(acc.y, 0.f);
        acc.z = fmaxf(acc.z, 0.f); acc.w = fmaxf(acc.w, 0.f);
        u32 h0, l0, h1, l1;
        split2(acc.x, acc.y, h0, l0);
        split2(acc.z, acc.w, h1, l1);
        const size_t o = (size_t)(rbase + r) * 512 + c0;
        *(uint2*)(xh + o) = make_uint2(h0, h1);
        *(uint2*)(xl + o) = make_uint2(l0, l1);
    }
}

// =====================================================================
// Embedding gather (cp.async.bulk, 256B per op) + pairwise interaction.
// Gather: 216 bulk copies/block vs 3456 cp16 ops -> 15x fewer LSU issues.
// Compute: 4x4 vector tiles, split-bf16 out into hh/hl (cols 64..414).
// =====================================================================
#define EROWS 8

__global__ void __launch_bounds__(256) embed_interact3(
    const u64* __restrict__ sidx, const float* __restrict__ emb,
    const float* __restrict__ dvec,
    u16* __restrict__ hh, u16* __restrict__ hl)
{
    extern __shared__ float Tsh[];
    __shared__ u64 mbar_store;
    __shared__ int s_is32;
    float4* T4 = (float4*)Tsh;
    const u32 sbase = smem_u32(Tsh);
    const u32 mbar  = smem_u32(&mbar_store);
    const int tid = threadIdx.x;
    const int rbase = blockIdx.x * EROWS;

    if (tid == 0) {
        int f = 0;
#pragma unroll
        for (int i = 0; i < 16; i++)
            if (sidx[i] >> 32) f = 1;
        s_is32 = f;
        asm volatile("mbarrier.init.shared.b64 [%0], 1;" :: "r"(mbar) : "memory");
    }
    __syncthreads();
    if (tid == 0) {
        // expect all gather bytes: (EROWS*26 + EROWS) * 256
        asm volatile("mbarrier.arrive.expect_tx.shared.b64 _, [%0], %1;"
                     :: "r"(mbar), "r"((u32)((EROWS * 27) * 256)) : "memory");
    }
    __syncthreads();
    const bool is32 = (s_is32 != 0);
    const int* sidx32 = (const int*)sidx;

    // 216 bulk copies: tid < EROWS*26 -> embedding row; next EROWS -> d vector
    if (tid < EROWS * 26) {
        const int r = tid / 26, t = tid - r * 26;
        long long idx;
        if (is32) idx = (long long)sidx32[(rbase + r) * 26 + t];
        else      idx = (long long)sidx[(rbase + r) * 26 + t];
        cpbulk256(sbase + (u32)((r * 28 + t) * 272),
                  emb + ((size_t)t * VOCABSZ + (size_t)idx) * 64, mbar);
    } else if (tid < EROWS * 27) {
        const int r = tid - EROWS * 26;
        cpbulk256(sbase + (u32)((r * 28 + 26) * 272),
                  dvec + (size_t)(rbase + r) * 64, mbar);
    }
    // zero pad vector 27 (plain stores)
    for (int u = tid; u < EROWS * 16; u += 256) {
        const int r = u >> 4, f = u & 15;
        T4[(r * 28 + 27) * 17 + f] = make_float4(0.f, 0.f, 0.f, 0.f);
    }
    // wait for all bulk transactions (parity 0, acquire)
    {
        u32 done;
        asm volatile(
            "{\n\t.reg .pred p;\n\t"
            "mbarrier.try_wait.parity.acquire.cta.shared::cta.b64 p, [%1], 0;\n\t"
            "selp.b32 %0, 1, 0, p;\n\t}"
            : "=r"(done) : "r"(mbar) : "memory");
        if (!done) {
            asm volatile(
                "{\n\t.reg .pred P;\n"
                "WL_%=:\n\t"
                "mbarrier.try_wait.parity.acquire.cta.shared::cta.b64 P, [%0], 0, 0x989680;\n\t"
                "@P bra WD_%=;\n\t"
                "bra WL_%=;\n"
                "WD_%=:\n\t}"
                :: "r"(mbar) : "memory");
        }
    }
    __syncthreads();

    const int task = tid;
    if (task < EROWS * 28) {
        const int r = task / 28, tt = task - r * 28;
        const int grow = rbase + r;
        u16* hrh = hh + (size_t)grow * 448 + 64;
        u16* hrl = hl + (size_t)grow * 448 + 64;
        const float4* bb = T4 + (size_t)r * 28 * 17;

        if (tt < 21) {
            int ti = 1;
            while ((ti * (ti + 1)) / 2 <= tt) ti++;
            const int tj = tt - ti * (ti - 1) / 2;
            const float4* Ti = bb + (4 * ti) * 17;
            const float4* Tj = bb + (4 * tj) * 17;
            float a[4][4];
#pragma unroll
            for (int ii = 0; ii < 4; ii++)
#pragma unroll
                for (int jj = 0; jj < 4; jj++) a[ii][jj] = 0.f;
#pragma unroll
            for (int f = 0; f < 16; f++) {
                float4 x[4], y[4];
#pragma unroll
                for (int ii = 0; ii < 4; ii++) x[ii] = Ti[ii * 17 + f];
#pragma unroll
                for (int jj = 0; jj < 4; jj++) y[jj] = Tj[jj * 17 + f];
#pragma unroll
                for (int ii = 0; ii < 4; ii++)
#pragma unroll
                    for (int jj = 0; jj < 4; jj++)
                        a[ii][jj] += x[ii].x * y[jj].x + x[ii].y * y[jj].y
                                   + x[ii].z * y[jj].z + x[ii].w * y[jj].w;
            }
#pragma unroll
            for (int ii = 0; ii < 4; ii++) {
                const int i = 4 * ti + ii;
                if (i < 27) {
                    const int base_i = i * (i - 1) / 2;
#pragma unroll
                    for (int jj = 0; jj < 4; jj++) {
                        const int j = 4 * tj + jj;
                        u32 h, l;
                        split2(a[ii][jj], 0.f, h, l);
                        hrh[base_i + j] = (u16)h;
                        hrl[base_i + j] = (u16)l;
                    }
                }
            }
        } else {
            const int ti = tt - 21;
            const float4* Ti = bb + (4 * ti) * 17;
            float a[6];
#pragma unroll
            for (int p = 0; p < 6; p++) a[p] = 0.f;
#pragma unroll
            for (int f = 0; f < 16; f++) {
                float4 x[4];
#pragma unroll
                for (int ii = 0; ii < 4; ii++) x[ii] = Ti[ii * 17 + f];
                a[0] += x[1].x * x[0].x + x[1].y * x[0].y + x[1].z * x[0].z + x[1].w * x[0].w;
                a[1] += x[2].x * x[0].x + x[2].y * x[0].y + x[2].z * x[0].z + x[2].w * x[0].w;
                a[2] += x[2].x * x[1].x + x[2].y * x[1].y + x[2].z * x[1].z + x[2].w * x[1].w;
                a[3] += x[3].x * x[0].x + x[3].y * x[0].y + x[3].z * x[0].z + x[3].w * x[0].w;
                a[4] += x[3].x * x[1].x + x[3].y * x[1].y + x[3].z * x[1].z + x[3].w * x[1].w;
                a[5] += x[3].x * x[2].x + x[3].y * x[2].y + x[3].z * x[2].z + x[3].w * x[2].w;
            }
            const int pi[6] = {1, 2, 2, 3, 3, 3};
            const int pj[6] = {0, 0, 1, 0, 1, 2};
#pragma unroll
            for (int p = 0; p < 6; p++) {
                const int i = 4 * ti + pi[p], j = 4 * ti + pj[p];
                if (i < 27) {
                    u32 h, l;
                    split2(a[p], 0.f, h, l);
                    hrh[i * (i - 1) / 2 + j] = (u16)h;
                    hrl[i * (i - 1) / 2 + j] = (u16)l;
                }
            }
        }
    }
}

// =====================================================================
// launch
// =====================================================================
extern "C" void kernel_launch(void* const* d_in, const int* in_sizes, int n_in,
                              void* d_out, int out_size)
{
    const float* dense = (const float*)d_in[0];
    const u64*   sidx  = (const u64*)  d_in[1];
    const float* emb   = (const float*)d_in[2];
    const float* Wb0 = (const float*)d_in[3];  const float* bb0 = (const float*)d_in[4];
    const float* Wb1 = (const float*)d_in[5];  const float* bb1 = (const float*)d_in[6];
    const float* Wb2 = (const float*)d_in[7];  const float* bb2 = (const float*)d_in[8];
    const float* Wt0 = (const float*)d_in[9];  const float* bt0 = (const float*)d_in[10];
    const float* Wt1 = (const float*)d_in[11]; const float* bt1 = (const float*)d_in[12];
    const float* Wt2 = (const float*)d_in[13]; const float* bt2 = (const float*)d_in[14];
    float* out = (float*)d_out;

    u16 *x0h, *x0l, *x1h, *x1l, *hh, *hl, *h1h, *h1l;
    float *dv;
    cudaGetSymbolAddress((void**)&x0h, g_x0h); cudaGetSymbolAddress((void**)&x0l, g_x0l);
    cudaGetSymbolAddress((void**)&x1h, g_x1h); cudaGetSymbolAddress((void**)&x1l, g_x1l);
    cudaGetSymbolAddress((void**)&dv,  g_d);
    cudaGetSymbolAddress((void**)&hh,  g_hh);  cudaGetSymbolAddress((void**)&hl,  g_hl);
    cudaGetSymbolAddress((void**)&h1h, g_h1h); cudaGetSymbolAddress((void**)&h1l, g_h1l);
    u16 *wb1h, *wb1l, *wb2h, *wb2l, *wt0h, *wt0l, *wt1h, *wt1l;
    cudaGetSymbolAddress((void**)&wb1h, g_Wb1h); cudaGetSymbolAddress((void**)&wb1l, g_Wb1l);
    cudaGetSymbolAddress((void**)&wb2h, g_Wb2h); cudaGetSymbolAddress((void**)&wb2l, g_Wb2l);
    cudaGetSymbolAddress((void**)&wt0h, g_Wt0h); cudaGetSymbolAddress((void**)&wt0l, g_Wt0l);
    cudaGetSymbolAddress((void**)&wt1h, g_Wt1h); cudaGetSymbolAddress((void**)&wt1l, g_Wt1l);

    // dynamic smem opt-in (idempotent, non-stream API: capture-safe)
    const int SM256 = 3 * (256 + 2 * 256) * 40 * 2;   // 184,320 B
    const int SM128 = 2 * (256 + 2 * 128) * 40 * 2;   //  81,920 B
    const int SM64  = 3 * (256 + 2 *  64) * 40 * 2;   //  92,160 B
    const int SMEI  = EROWS * 28 * 68 * 4;            //  60,928 B
    cudaFuncSetAttribute((const void*)gemm_mma<256, 128, 1, 2>,
                         cudaFuncAttributeMaxDynamicSharedMemorySize, SM128);
    cudaFuncSetAttribute((const void*)gemm_mma<512, 64, 2, 3>,
                         cudaFuncAttributeMaxDynamicSharedMemorySize, SM64);
    cudaFuncSetAttribute((const void*)gemm_mma<512, 256, 1, 3>,
                         cudaFuncAttributeMaxDynamicSharedMemorySize, SM256);
    cudaFuncSetAttribute((const void*)gemm_mma<512, 256, 3, 3>,
                         cudaFuncAttributeMaxDynamicSharedMemorySize, SM256);
    cudaFuncSetAttribute((const void*)embed_interact3,
                         cudaFuncAttributeMaxDynamicSharedMemorySize, SMEI);

    // 0) weight transpose + bf16 split
    prep_all<<<248, 256>>>(Wb1, Wb2, Wt0, Wt1,
                           wb1h, wb1l, wb2h, wb2l, wt0h, wt0l, wt1h, wt1l);

    // 1) bottom L0: dense -> x0 (split)
    bot0_kernel<<<BATCH / 32, 256>>>(dense, Wb0, bb0, x0h, x0l);

    // 2) bottom L1: x0 -> x1 (split out)  N=256 K=512
    gemm_mma<256, 128, 1, 2><<<dim3(2, BATCH / 128), 256, SM128>>>(
        x0h, x0l, 512, wb1h, wb1l, bb1, nullptr, 0, x1h, x1l, 256, 16,
        nullptr, nullptr, nullptr);

    // 3) bottom L2: x1 -> d fp32 + hh/hl cols 0..63  N=64 K=256
    gemm_mma<512, 64, 2, 3><<<dim3(1, BATCH / 128), 512, SM64>>>(
        x1h, x1l, 256, wb2h, wb2l, bb2, dv, 64, hh, hl, 448, 8,
        nullptr, nullptr, nullptr);

    // 4) embedding gather (bulk) + interaction -> hh/hl cols 64..414
    embed_interact3<<<BATCH / EROWS, 256, SMEI>>>(sidx, emb, dv, hh, hl);

    // 5) top L0: h -> h1 (split out)  N=512 K=448
    gemm_mma<512, 256, 1, 3><<<dim3(2, BATCH / 128), 512, SM256>>>(
        hh, hl, 448, wt0h, wt0l, bt0, nullptr, 0, h1h, h1l, 512, 14,
        nullptr, nullptr, nullptr);

    // 6) top L1 + final fused: h1 -> sigmoid(h2 . Wt2 + bt2) -> out
    gemm_mma<512, 256, 3, 3><<<dim3(1, BATCH / 128), 512, SM256>>>(
        h1h, h1l, 512, wt1h, wt1l, bt1, nullptr, 0, nullptr, nullptr, 0, 16,
        out, Wt2, bt2);
}